// round 11
// baseline (speedup 1.0000x reference)
#include <cuda_runtime.h>
#include <cuda_bf16.h>
#include <math.h>
#include <stdint.h>

#define BB 32
#define NN 196
#define TT 128
#define DH 512
#define VV 10000
#define VPAD 10112
#define GRID_P 148
#define NH 18              // bankH rows/CTA: Whh(2048)+Wh(512)=2560 <= 148*18
#define NX 14              // bankX rows/CTA: Wih ctx cols 2048 <= 148*14
#define HSTR4 129          // float4 stride of h_s rows (516 floats, conflict-free)
#define DYN_FLOATS ((NH + NX) * 512 + 32 * 516)

// hierarchical barrier layout (unsigned words; 256B line stride to dodge bit-7 LTS pairing)
#define NGRP 19
#define SY_GEN  0
#define SY_ROOT 64
#define SY_GRP  128                   // + g*64
#define SY_MINI (128 + NGRP * 64)     // + b*64
#define SY_TOTAL (SY_MINI + BB * 64)

typedef __nv_bfloat16 bf16;

// ---------------- device scratch (static, no allocation) ----------------
__device__ float g_keys[BB * NN * DH];
__device__ float g_wk  [BB * NN * DH];
__device__ float g_Gx  [BB * TT * 4 * DH];
__device__ float g_h   [BB * DH];
__device__ float g_c   [BB * DH];
__device__ float g_hwh [BB * DH];
__device__ float g_gh  [BB * 4 * DH];
__device__ float g_gx  [BB * 4 * DH];
__device__ float g_ctx [BB * DH];
__device__ float g_ctxp[4][BB * DH];
__device__ float g_cm[BB * 4], g_cs[BB * 4];
__device__ unsigned g_sync[SY_TOTAL];
__device__ bf16 g_hall_hi[BB * TT * DH], g_hall_lo[BB * TT * DH];
__device__ bf16 g_w_hi[VPAD * DH], g_w_lo[VPAD * DH];   // rows >= VV stay zero
__device__ bf16 g_x_hi[BB * TT * DH], g_x_lo[BB * TT * DH];
__device__ bf16 g_p_hi[BB * NN * 768], g_p_lo[BB * NN * 768];
__device__ bf16 g_kvw_hi[512 * 768], g_kvw_lo[512 * 768];
__device__ bf16 g_awk_hi[512 * 512], g_awk_lo[512 * 512];
__device__ bf16 g_wih_hi[2048 * 512], g_wih_lo[2048 * 512];
__device__ bf16 g_keys_hi[BB * NN * DH], g_keys_lo[BB * NN * DH];

__device__ __forceinline__ float fast_tanh(float x) {
    float y; asm("tanh.approx.f32 %0, %1;" : "=f"(y) : "f"(x)); return y;
}
__device__ __forceinline__ float sigm(float x) { return 1.f / (1.f + expf(-x)); }
__device__ __forceinline__ void split_bf16(float v, bf16* hi, bf16* lo) {
    const bf16 h = __float2bfloat16(v);
    *hi = h;
    *lo = __float2bfloat16(v - __bfloat162float(h));
}

// ---------------- mma.sync helpers (sm_80 PTX — valid at compute_103) ----------------
__device__ __forceinline__ uint32_t smem_u32(const void* p) {
    uint32_t a;
    asm("{ .reg .u64 t; cvta.to.shared.u64 t, %1; cvt.u32.u64 %0, t; }" : "=r"(a) : "l"(p));
    return a;
}
__device__ __forceinline__ void ldsm4(uint32_t* r, uint32_t addr) {
    asm volatile("ldmatrix.sync.aligned.m8n8.x4.shared.b16 {%0,%1,%2,%3}, [%4];"
        : "=r"(r[0]), "=r"(r[1]), "=r"(r[2]), "=r"(r[3]) : "r"(addr));
}
__device__ __forceinline__ void mma16816(float* c, const uint32_t* a, const uint32_t* b) {
    asm volatile("mma.sync.aligned.m16n8k16.row.col.f32.bf16.bf16.f32 "
        "{%0,%1,%2,%3}, {%4,%5,%6,%7}, {%8,%9}, {%0,%1,%2,%3};"
        : "+f"(c[0]), "+f"(c[1]), "+f"(c[2]), "+f"(c[3])
        : "r"(a[0]), "r"(a[1]), "r"(a[2]), "r"(a[3]), "r"(b[0]), "r"(b[1]));
}

// ---------------- generic split-bf16 MMA GEMM: C[M,N] = A@B^T (+b1+b2) ----------------
#define LSTR 40
__global__ __launch_bounds__(256) void mma_nt(
    const bf16* __restrict__ Ah, const bf16* __restrict__ Al,
    const bf16* __restrict__ Bh, const bf16* __restrict__ Bl,
    const float* __restrict__ bias1, const float* __restrict__ bias2,
    float* __restrict__ C, int ldc, int nLimit, int kChunks, int ldA, int ldB,
    bf16* __restrict__ Chi, bf16* __restrict__ Clo)
{
    __shared__ bf16 sAh[128 * LSTR], sAl[128 * LSTR];
    __shared__ bf16 sBh[128 * LSTR], sBl[128 * LSTR];

    const int tid = threadIdx.x;
    const int wid = tid >> 5, lane = tid & 31;
    const int nBase = blockIdx.x * 128;
    const int mBase = blockIdx.y * 128;
    const int wm = (wid & 3) * 32;
    const int wn = (wid >> 2) * 64;

    const uint32_t uAh = smem_u32(sAh), uAl = smem_u32(sAl);
    const uint32_t uBh = smem_u32(sBh), uBl = smem_u32(sBl);

    float acc[2][8][4];
#pragma unroll
    for (int i = 0; i < 2; i++)
#pragma unroll
        for (int j = 0; j < 8; j++)
#pragma unroll
            for (int k = 0; k < 4; k++) acc[i][j][k] = 0.f;

    const int cr = tid >> 1;
    const int cs = (tid & 1) * 2;

    for (int ch = 0; ch < kChunks; ch++) {
        {
            const int goff = ch * 32 + cs * 8;
            const uint4* pAh = (const uint4*)(Ah + (size_t)(mBase + cr) * ldA + goff);
            const uint4* pAl = (const uint4*)(Al + (size_t)(mBase + cr) * ldA + goff);
            const uint4* pBh = (const uint4*)(Bh + (size_t)(nBase + cr) * ldB + goff);
            const uint4* pBl = (const uint4*)(Bl + (size_t)(nBase + cr) * ldB + goff);
            uint4* dAh = (uint4*)(sAh + cr * LSTR + cs * 8);
            uint4* dAl = (uint4*)(sAl + cr * LSTR + cs * 8);
            uint4* dBh = (uint4*)(sBh + cr * LSTR + cs * 8);
            uint4* dBl = (uint4*)(sBl + cr * LSTR + cs * 8);
            dAh[0] = pAh[0]; dAh[1] = pAh[1];
            dAl[0] = pAl[0]; dAl[1] = pAl[1];
            dBh[0] = pBh[0]; dBh[1] = pBh[1];
            dBl[0] = pBl[0]; dBl[1] = pBl[1];
        }
        __syncthreads();

#pragma unroll
        for (int ks = 0; ks < 2; ks++) {
            uint32_t ah[2][4], al[2][4], bh[8][2], bl[8][2];
#pragma unroll
            for (int mt = 0; mt < 2; mt++) {
                const uint32_t off =
                    ((wm + mt * 16 + (lane & 15)) * LSTR + ks * 16 + (lane >> 4) * 8) * 2;
                ldsm4(ah[mt], uAh + off);
                ldsm4(al[mt], uAl + off);
            }
#pragma unroll
            for (int p = 0; p < 4; p++) {
                const uint32_t off =
                    ((wn + p * 16 + ((lane >> 4) & 1) * 8 + (lane & 7)) * LSTR +
                     ks * 16 + ((lane >> 3) & 1) * 8) * 2;
                uint32_t r4[4];
                ldsm4(r4, uBh + off);
                bh[2 * p][0] = r4[0]; bh[2 * p][1] = r4[1];
                bh[2 * p + 1][0] = r4[2]; bh[2 * p + 1][1] = r4[3];
                ldsm4(r4, uBl + off);
                bl[2 * p][0] = r4[0]; bl[2 * p][1] = r4[1];
                bl[2 * p + 1][0] = r4[2]; bl[2 * p + 1][1] = r4[3];
            }
#pragma unroll
            for (int mt = 0; mt < 2; mt++)
#pragma unroll
                for (int nt = 0; nt < 8; nt++) {
                    mma16816(acc[mt][nt], ah[mt], bh[nt]);
                    mma16816(acc[mt][nt], ah[mt], bl[nt]);
                    mma16816(acc[mt][nt], al[mt], bh[nt]);
                }
        }
        __syncthreads();
    }

    const int erow = lane >> 2;
    const int ecol = (lane & 3) * 2;
#pragma unroll
    for (int mt = 0; mt < 2; mt++) {
#pragma unroll
        for (int nt = 0; nt < 8; nt++) {
            const int gn = nBase + wn + nt * 8 + ecol;
            if (gn >= nLimit) continue;
            float b0 = 0.f, b1 = 0.f;
            if (bias1) { b0 += bias1[gn]; b1 += bias1[gn + 1]; }
            if (bias2) { b0 += bias2[gn]; b1 += bias2[gn + 1]; }
            const int r0 = mBase + wm + mt * 16 + erow;
            const float v00 = acc[mt][nt][0] + b0, v01 = acc[mt][nt][1] + b1;
            const float v10 = acc[mt][nt][2] + b0, v11 = acc[mt][nt][3] + b1;
            if (C) {
                *(float2*)&C[(size_t)r0 * ldc + gn] = make_float2(v00, v01);
                *(float2*)&C[(size_t)(r0 + 8) * ldc + gn] = make_float2(v10, v11);
            }
            if (Chi) {
                const size_t i0 = (size_t)r0 * ldc + gn;
                const size_t i1 = (size_t)(r0 + 8) * ldc + gn;
                split_bf16(v00, &Chi[i0], &Clo[i0]);
                split_bf16(v01, &Chi[i0 + 1], &Clo[i0 + 1]);
                split_bf16(v10, &Chi[i1], &Clo[i1]);
                split_bf16(v11, &Chi[i1 + 1], &Clo[i1 + 1]);
            }
        }
    }
}

// ---------------- all input conversions + embedding gather ----------------
#define NB_GATH 8192
#define NB_OUTW 20000
#define NB_PTCH 18816
#define NB_KVW  1536
#define NB_AWK  1024
#define NB_WIH  4096
__global__ void gather_conv(const int* __restrict__ ids, const float* __restrict__ emb,
                            const float* __restrict__ outW, const float* __restrict__ patches,
                            const float* __restrict__ kvW, const float* __restrict__ aWk,
                            const float* __restrict__ Wih)
{
    int blk = blockIdx.x;
    const int tid = threadIdx.x;
    if (blk < NB_GATH) {
        const int i = blk * 256 + tid;
        const int d = i & (DH - 1);
        const int bt = i >> 9;
        split_bf16(emb[(size_t)ids[bt] * DH + d], &g_x_hi[i], &g_x_lo[i]);
        return;
    }
    blk -= NB_GATH;
    if (blk < NB_OUTW) {
        const int j = blk * 256 + tid;
        if (j < VV * DH) split_bf16(outW[j], &g_w_hi[j], &g_w_lo[j]);
        return;
    }
    blk -= NB_OUTW;
    if (blk < NB_PTCH) {
        const int j = blk * 256 + tid;
        split_bf16(patches[j], &g_p_hi[j], &g_p_lo[j]);
        return;
    }
    blk -= NB_PTCH;
    if (blk < NB_KVW) {
        const int j = blk * 256 + tid;
        split_bf16(kvW[j], &g_kvw_hi[j], &g_kvw_lo[j]);
        return;
    }
    blk -= NB_KVW;
    if (blk < NB_AWK) {
        const int j = blk * 256 + tid;
        split_bf16(aWk[j], &g_awk_hi[j], &g_awk_lo[j]);
        return;
    }
    blk -= NB_AWK;
    {
        const int j = blk * 256 + tid;
        const int r = j >> 9, c = j & 511;
        split_bf16(Wih[(size_t)r * 1024 + c], &g_wih_hi[j], &g_wih_lo[j]);
    }
}

// ---------------- persistent decode loop ----------------
__global__ __launch_bounds__(256, 1) void decode_loop(
    const float* __restrict__ Wh, const float* __restrict__ av,
    const float* __restrict__ Wih, const float* __restrict__ Whh,
    const float* __restrict__ lnw, const float* __restrict__ lnb,
    const float* __restrict__ cls,
    const float* __restrict__ ihW, const float* __restrict__ ihb,
    const float* __restrict__ icW, const float* __restrict__ icb)
{
    extern __shared__ float smem[];
    float* wH = smem;                                  // [NH][512]
    float* wX = smem + NH * 512;                       // [NX][512]
    float4* hs4 = (float4*)(smem + (NH + NX) * 512);   // [32][HSTR4]

    __shared__ float s_v[512];
    __shared__ float s_hwh[512];
    __shared__ float s_sc[49];
    __shared__ float s_e[64];
    __shared__ float s_r0[8], s_r1[8], s_mv[2];

    const int tid = threadIdx.x;
    const int bid = blockIdx.x;
    const int warp = tid >> 5, lane = tid & 31;
    const int gwarp = bid * 8 + warp;
    const int b32 = tid & 31, q = tid >> 5;
    unsigned bt = 0;

#pragma unroll
    for (int i = 0; i < NH; i++) {
        const int r = bid * NH + i;
        const float* src = (r < 2048) ? (Whh + (size_t)r * 512)
                          : (r < 2560) ? (Wh + (size_t)(r - 2048) * 512) : nullptr;
        if (src) for (int k = tid; k < 512; k += 256) wH[i * 512 + k] = src[k];
    }
#pragma unroll
    for (int i = 0; i < NX; i++) {
        const int r = bid * NX + i;
        if (r < 2048)
            for (int k = tid; k < 512; k += 256) wX[i * 512 + k] = Wih[(size_t)r * 1024 + 512 + k];
    }
    for (int k = tid; k < 512; k += 256) s_v[k] = av[k];

    // hierarchical grid barrier: group arrive -> root arrive -> generation publish
    const unsigned grp = (unsigned)bid >> 3;                  // 0..18
    const unsigned gsz = (grp < 18u) ? 8u : 4u;
    auto gsync = [&](unsigned target) {
        __syncthreads();
        if (tid == 0) {
            __threadfence();
            const unsigned a = atomicAdd(&g_sync[SY_GRP + grp * 64], 1u);
            if (a == gsz * target - 1u) {
                const unsigned r = atomicAdd(&g_sync[SY_ROOT], 1u);
                if (r == (unsigned)NGRP * target - 1u)
                    atomicExch(&g_sync[SY_GEN], target);
            }
            while (*(volatile unsigned*)&g_sync[SY_GEN] < target) {}
            __threadfence();
        }
        __syncthreads();
    };

    // ---- h0/c0 (folded) ----
    for (int j = gwarp; j < 2 * BB * DH; j += GRID_P * 8) {
        const int sel = (j >= BB * DH);
        const int r = sel ? j - BB * DH : j;
        const int b = r >> 9, d = r & (DH - 1);
        const float4* W4 = (const float4*)((sel ? icW : ihW) + (size_t)d * 768);
        const float4* x4 = (const float4*)(cls + (size_t)b * 768);
        float acc = 0.f;
#pragma unroll
        for (int p = 0; p < 6; p++) {
            float4 w = W4[lane + 32 * p];
            float4 x = x4[lane + 32 * p];
            acc += w.x * x.x + w.y * x.y + w.z * x.z + w.w * x.w;
        }
#pragma unroll
        for (int o = 16; o; o >>= 1) acc += __shfl_xor_sync(0xffffffffu, acc, o);
        if (lane == 0) {
            if (sel) g_c[b * DH + d] = acc + icb[d];
            else     g_h[b * DH + d] = acc + ihb[d];
        }
    }
    gsync(++bt);

    for (int t = 0; t < TT; t++) {
        // ======== Phase W: h-gates + hwh (weights in smem) ========
        {
            const float4* hsrc = (const float4*)g_h;
            for (int idx = tid; idx < 32 * 128; idx += 256)
                hs4[(idx >> 7) * HSTR4 + (idx & 127)] = hsrc[idx];
        }
        __syncthreads();
        {
            const float4* hp = hs4 + b32 * HSTR4;
            float4 a0 = make_float4(0.f, 0.f, 0.f, 0.f), a1 = a0, a2 = a0;
            const float4* w0 = (const float4*)(wH + q * 512);
            const float4* w1 = (const float4*)(wH + (q + 8) * 512);
            const float4* w2 = (const float4*)(wH + ((q < 2) ? (q + 16) : 0) * 512);
#pragma unroll 8
            for (int k = 0; k < 128; k++) {
                const float4 h = hp[k];
                const float4 x = w0[k];
                a0.x = fmaf(h.x, x.x, a0.x); a0.y = fmaf(h.y, x.y, a0.y);
                a0.z = fmaf(h.z, x.z, a0.z); a0.w = fmaf(h.w, x.w, a0.w);
                const float4 y = w1[k];
                a1.x = fmaf(h.x, y.x, a1.x); a1.y = fmaf(h.y, y.y, a1.y);
                a1.z = fmaf(h.z, y.z, a1.z); a1.w = fmaf(h.w, y.w, a1.w);
                const float4 z = w2[k];
                a2.x = fmaf(h.x, z.x, a2.x); a2.y = fmaf(h.y, z.y, a2.y);
                a2.z = fmaf(h.z, z.z, a2.z); a2.w = fmaf(h.w, z.w, a2.w);
            }
            const float s0 = (a0.x + a0.y) + (a0.z + a0.w);
            const float s1 = (a1.x + a1.y) + (a1.z + a1.w);
            const float s2 = (a2.x + a2.y) + (a2.z + a2.w);
            int r = bid * NH + q;
            if (r < 2048) g_gh[b32 * 2048 + r] = s0;
            else if (r < 2560) g_hwh[b32 * 512 + r - 2048] = s0;
            r = bid * NH + q + 8;
            if (r < 2048) g_gh[b32 * 2048 + r] = s1;
            else if (r < 2560) g_hwh[b32 * 512 + r - 2048] = s1;
            if (q < 2) {
                r = bid * NH + q + 16;
                if (r < 2048) g_gh[b32 * 2048 + r] = s2;
                else if (r < 2560) g_hwh[b32 * 512 + r - 2048] = s2;
            }
        }
        gsync(++bt);

        // ======== Phase B: chunk scores + partial ctx + per-b combine ========
        if (bid < BB * 4) {
            const int b = bid >> 2, p = bid & 3;
            for (int k = tid; k < 512; k += 256) s_hwh[k] = g_hwh[b * 512 + k];
            __syncthreads();

            for (int n = warp; n < 49; n += 8) {
                const int ng = p * 49 + n;
                const float4* wk4 = (const float4*)(g_wk + ((size_t)(b * NN + ng)) * 512);
                const float4* hw4 = (const float4*)s_hwh;
                const float4* v4  = (const float4*)s_v;
                float s = 0.f;
#pragma unroll
                for (int i = 0; i < 4; i++) {
                    const float4 a = wk4[lane + 32 * i];
                    const float4 c = hw4[lane + 32 * i];
                    const float4 w = v4[lane + 32 * i];
                    s += fast_tanh(a.x + c.x) * w.x + fast_tanh(a.y + c.y) * w.y +
                         fast_tanh(a.z + c.z) * w.z + fast_tanh(a.w + c.w) * w.w;
                }
#pragma unroll
                for (int o = 16; o; o >>= 1) s += __shfl_xor_sync(0xffffffffu, s, o);
                if (lane == 0) s_sc[n] = s;
            }
            __syncthreads();

            if (warp == 0) {
                const float x0 = (lane < 49) ? s_sc[lane] : -1e30f;
                const float x1 = (lane + 32 < 49) ? s_sc[lane + 32] : -1e30f;
                float m = fmaxf(x0, x1);
#pragma unroll
                for (int o = 16; o; o >>= 1) m = fmaxf(m, __shfl_xor_sync(0xffffffffu, m, o));
                const float e0 = (lane < 49) ? __expf(x0 - m) : 0.f;
                const float e1 = (lane + 32 < 49) ? __expf(x1 - m) : 0.f;
                if (lane < 49) s_e[lane] = e0;
                if (lane + 32 < 49) s_e[lane + 32] = e1;
                float su = e0 + e1;
#pragma unroll
                for (int o = 16; o; o >>= 1) su += __shfl_xor_sync(0xffffffffu, su, o);
                if (lane == 0) { g_cm[b * 4 + p] = m; g_cs[b * 4 + p] = su; }
            }
            __syncthreads();

#pragma unroll
            for (int u = 0; u < 2; u++) {
                const int d = tid + 256 * u;
                const float* Kp = g_keys + ((size_t)(b * NN + p * 49)) * 512 + d;
                float a = 0.f;
#pragma unroll 7
                for (int i = 0; i < 49; i++) a = fmaf(s_e[i], Kp[(size_t)i * 512], a);
                g_ctxp[p][b * 512 + d] = a;
            }

            __syncthreads();
            if (tid == 0) {
                __threadfence();
                atomicAdd(&g_sync[SY_MINI + b * 64], 1u);
                while (*(volatile unsigned*)&g_sync[SY_MINI + b * 64] < 4u * (unsigned)(t + 1)) {}
                __threadfence();
            }
            __syncthreads();

            if (tid < 128) {
                const int d = p * 128 + tid;
                const float m0 = g_cm[b*4+0], m1 = g_cm[b*4+1], m2 = g_cm[b*4+2], m3 = g_cm[b*4+3];
                const float m = fmaxf(fmaxf(m0, m1), fmaxf(m2, m3));
                const float e0 = __expf(m0 - m), e1 = __expf(m1 - m);
                const float e2 = __expf(m2 - m), e3 = __expf(m3 - m);
                const float den = e0 * g_cs[b*4+0] + e1 * g_cs[b*4+1] +
                                  e2 * g_cs[b*4+2] + e3 * g_cs[b*4+3];
                const float v = e0 * g_ctxp[0][b*512+d] + e1 * g_ctxp[1][b*512+d] +
                                e2 * g_ctxp[2][b*512+d] + e3 * g_ctxp[3][b*512+d];
                g_ctx[b * 512 + d] = v / den;
            }
        }
        gsync(++bt);

        // ======== Phase C: ctx-gates (weights in smem) ========
        {
            const float4* csrc = (const float4*)g_ctx;
            for (int idx = tid; idx < 32 * 128; idx += 256)
                hs4[(idx >> 7) * HSTR4 + (idx & 127)] = csrc[idx];
        }
        __syncthreads();
        {
            const float4* cp = hs4 + b32 * HSTR4;
            float4 a0 = make_float4(0.f, 0.f, 0.f, 0.f), a1 = a0;
            const float4* w0 = (const float4*)(wX + q * 512);
            const float4* w1 = (const float4*)(wX + ((q + 8 < NX) ? (q + 8) : 0) * 512);
#pragma unroll 8
            for (int k = 0; k < 128; k++) {
                const float4 h = cp[k];
                const float4 x = w0[k];
                a0.x = fmaf(h.x, x.x, a0.x); a0.y = fmaf(h.y, x.y, a0.y);
                a0.z = fmaf(h.z, x.z, a0.z); a0.w = fmaf(h.w, x.w, a0.w);
                const float4 y = w1[k];
                a1.x = fmaf(h.x, y.x, a1.x); a1.y = fmaf(h.y, y.y, a1.y);
                a1.z = fmaf(h.z, y.z, a1.z); a1.w = fmaf(h.w, y.w, a1.w);
            }
            const float s0 = (a0.x + a0.y) + (a0.z + a0.w);
            const float s1 = (a1.x + a1.y) + (a1.z + a1.w);
            int r = bid * NX + q;
            if (r < 2048) g_gx[b32 * 2048 + r] = s0;
            if (q + 8 < NX) {
                r = bid * NX + q + 8;
                if (r < 2048) g_gx[b32 * 2048 + r] = s1;
            }
        }
        gsync(++bt);

        // ======== Phase D: cell + LayerNorm (32 blocks) ========
        if (bid < BB) {
            const int b = bid;
            const float* Gx = g_Gx + ((size_t)(b * TT + t)) * 2048;
            const float* Gh = g_gh + (size_t)b * 2048;
            const float* Gc = g_gx + (size_t)b * 2048;
            float hr[2];
            float sum = 0.f, ssq = 0.f;
#pragma unroll
            for (int u = 0; u < 2; u++) {
                const int d = tid + 256 * u;
                const float gi = Gx[d]        + Gh[d]        + Gc[d];
                const float gf = Gx[512 + d]  + Gh[512 + d]  + Gc[512 + d];
                const float gg = Gx[1024 + d] + Gh[1024 + d] + Gc[1024 + d];
                const float go = Gx[1536 + d] + Gh[1536 + d] + Gc[1536 + d];
                const float c_old = g_c[b * DH + d];
                const float cn = sigm(gf) * c_old + sigm(gi) * tanhf(gg);
                g_c[b * DH + d] = cn;
                const float h = sigm(go) * tanhf(cn);
                hr[u] = h; sum += h; ssq += h * h;
            }
#pragma unroll
            for (int o = 16; o; o >>= 1) {
                sum += __shfl_xor_sync(0xffffffffu, sum, o);
                ssq += __shfl_xor_sync(0xffffffffu, ssq, o);
            }
            if (lane == 0) { s_r0[warp] = sum; s_r1[warp] = ssq; }
            __syncthreads();
            if (tid < 8) {
                float s = s_r0[tid], qq = s_r1[tid];
#pragma unroll
                for (int o = 4; o; o >>= 1) {
                    s += __shfl_xor_sync(0x000000ffu, s, o);
                    qq += __shfl_xor_sync(0x000000ffu, qq, o);
                }
                if (tid == 0) { s_mv[0] = s * (1.f / DH); s_mv[1] = qq * (1.f / DH); }
            }
            __syncthreads();
            const float mu = s_mv[0];
            const float var = s_mv[1] - mu * mu;
            const float rstd = rsqrtf(var + 1e-5f);
#pragma unroll
            for (int u = 0; u < 2; u++) {
                const int d = tid + 256 * u;
                const float h = (hr[u] - mu) * rstd * lnw[d] + lnb[d];
                g_h[b * DH + d] = h;
                const size_t idx = ((size_t)(b * TT + t)) * DH + d;
                split_bf16(h, &g_hall_hi[idx], &g_hall_lo[idx]);
            }
        }
        gsync(++bt);
    }
}

// ---------------- launch ----------------
extern "C" void kernel_launch(void* const* d_in, const int* in_sizes, int n_in,
                              void* d_out, int out_size)
{
    const float* patches = (const float*)d_in[0];
    const float* cls     = (const float*)d_in[1];
    const int*   tgt     = (const int*)  d_in[2];
    const float* emb     = (const float*)d_in[3];
    const float* kvW     = (const float*)d_in[4];
    const float* kvb     = (const float*)d_in[5];
    const float* ihW     = (const float*)d_in[6];
    const float* ihb     = (const float*)d_in[7];
    const float* icW     = (const float*)d_in[8];
    const float* icb     = (const float*)d_in[9];
    const float* aWh     = (const float*)d_in[10];
    const float* aWk     = (const float*)d_in[11];
    const float* av      = (const float*)d_in[12];
    const float* Wih     = (const float*)d_in[13];
    const float* Whh     = (const float*)d_in[14];
    const float* bih     = (const float*)d_in[15];
    const float* bhh     = (const float*)d_in[16];
    const float* lnw     = (const float*)d_in[17];
    const float* lnb     = (const float*)d_in[18];
    const float* outW    = (const float*)d_in[19];
    const float* outb    = (const float*)d_in[20];
    float* out = (float*)d_out;

    float *keys, *wk, *Gx;
    bf16 *xh, *xl, *ph, *pl, *kvh, *kvl, *awh, *awl, *wih_h, *wih_l;
    bf16 *kh, *kl, *hh, *hl, *wh, *wl;
    unsigned* syncp;
    cudaGetSymbolAddress((void**)&keys, g_keys);
    cudaGetSymbolAddress((void**)&wk,   g_wk);
    cudaGetSymbolAddress((void**)&Gx,   g_Gx);
    cudaGetSymbolAddress((void**)&syncp, g_sync);
    cudaGetSymbolAddress((void**)&xh, g_x_hi);   cudaGetSymbolAddress((void**)&xl, g_x_lo);
    cudaGetSymbolAddress((void**)&ph, g_p_hi);   cudaGetSymbolAddress((void**)&pl, g_p_lo);
    cudaGetSymbolAddress((void**)&kvh, g_kvw_hi); cudaGetSymbolAddress((void**)&kvl, g_kvw_lo);
    cudaGetSymbolAddress((void**)&awh, g_awk_hi); cudaGetSymbolAddress((void**)&awl, g_awk_lo);
    cudaGetSymbolAddress((void**)&wih_h, g_wih_hi); cudaGetSymbolAddress((void**)&wih_l, g_wih_lo);
    cudaGetSymbolAddress((void**)&kh, g_keys_hi); cudaGetSymbolAddress((void**)&kl, g_keys_lo);
    cudaGetSymbolAddress((void**)&hh, g_hall_hi); cudaGetSymbolAddress((void**)&hl, g_hall_lo);
    cudaGetSymbolAddress((void**)&wh, g_w_hi);    cudaGetSymbolAddress((void**)&wl, g_w_lo);

    cudaMemsetAsync(syncp, 0, SY_TOTAL * sizeof(unsigned));

    cudaFuncSetAttribute(decode_loop, cudaFuncAttributeMaxDynamicSharedMemorySize,
                         DYN_FLOATS * (int)sizeof(float));

    gather_conv<<<NB_GATH + NB_OUTW + NB_PTCH + NB_KVW + NB_AWK + NB_WIH, 256>>>(
        tgt, emb, outW, patches, kvW, aWk, Wih);

    // keys = patches @ kvW^T + kvb     [6272 x 512], K=768 (also emit bf16 split)
    mma_nt<<<dim3(4, 49), 256>>>(ph, pl, kvh, kvl, kvb, nullptr,
                                 keys, 512, 512, 24, 768, 768, kh, kl);
    // wk = keys @ aWk^T                [6272 x 512], K=512
    mma_nt<<<dim3(4, 49), 256>>>(kh, kl, awh, awl, nullptr, nullptr,
                                 wk, 512, 512, 16, 512, 512, nullptr, nullptr);
    // Gx = x @ Wih_x^T + b_ih + b_hh   [4096 x 2048], K=512
    mma_nt<<<dim3(16, 32), 256>>>(xh, xl, wih_h, wih_l, bih, bhh,
                                  Gx, 2048, 2048, 16, 512, 512, nullptr, nullptr);

    decode_loop<<<GRID_P, 256, DYN_FLOATS * sizeof(float)>>>(
        aWh, av, Wih, Whh, lnw, lnb, cls, ihW, ihb, icW, icb);

    // logits = hall @ outW^T + outb    [4096 x 10000], K=512
    mma_nt<<<dim3(79, 32), 256>>>(hh, hl, wh, wl, outb, nullptr,
                                  out, VV, VV, 16, 512, 512, nullptr, nullptr);
}

// round 12
// speedup vs baseline: 1.0489x; 1.0489x over previous
#include <cuda_runtime.h>
#include <cuda_bf16.h>
#include <math.h>
#include <stdint.h>

#define BB 32
#define NN 196
#define TT 128
#define DH 512
#define VV 10000
#define VPAD 10112
#define GRID_P 148
#define NH 18              // bankH rows/CTA: Whh(2048)+Wh(512)=2560 <= 148*18
#define NX 14              // bankX rows/CTA: Wih ctx cols 2048 <= 148*14
#define HSTR4 129          // float4 stride of h_s rows (516 floats, conflict-free)
#define DYN_FLOATS ((NH + NX) * 512 + 32 * 516)

typedef __nv_bfloat16 bf16;

// ---------------- device scratch (static, no allocation) ----------------
__device__ float g_keys[BB * NN * DH];
__device__ float g_wk  [BB * NN * DH];
__device__ float g_Gx  [BB * TT * 4 * DH];
__device__ float g_h   [BB * DH];
__device__ float g_c   [BB * DH];
__device__ float g_hwh [BB * DH];
__device__ float g_gh  [BB * 4 * DH];
__device__ float g_gx  [BB * 4 * DH];
__device__ float g_ctx [BB * DH];
__device__ float g_ctxp[4][BB * DH];
__device__ float g_cm[BB * 4], g_cs[BB * 4];
__device__ unsigned g_sync[2 + BB * 32];     // [0]=count [2+b*32]=mini-barriers
__device__ bf16 g_hall_hi[BB * TT * DH], g_hall_lo[BB * TT * DH];
__device__ bf16 g_w_hi[VPAD * DH], g_w_lo[VPAD * DH];   // rows >= VV stay zero
__device__ bf16 g_x_hi[BB * TT * DH], g_x_lo[BB * TT * DH];
__device__ bf16 g_p_hi[BB * NN * 768], g_p_lo[BB * NN * 768];
__device__ bf16 g_kvw_hi[512 * 768], g_kvw_lo[512 * 768];
__device__ bf16 g_awk_hi[512 * 512], g_awk_lo[512 * 512];
__device__ bf16 g_wih_hi[2048 * 512], g_wih_lo[2048 * 512];
__device__ bf16 g_keys_hi[BB * NN * DH], g_keys_lo[BB * NN * DH];

__device__ __forceinline__ float fast_tanh(float x) {
    float y; asm("tanh.approx.f32 %0, %1;" : "=f"(y) : "f"(x)); return y;
}
__device__ __forceinline__ float sigm(float x) { return 1.f / (1.f + expf(-x)); }
__device__ __forceinline__ void split_bf16(float v, bf16* hi, bf16* lo) {
    const bf16 h = __float2bfloat16(v);
    *hi = h;
    *lo = __float2bfloat16(v - __bfloat162float(h));
}

// ---------------- mma.sync helpers (sm_80 PTX — valid at compute_103) ----------------
__device__ __forceinline__ uint32_t smem_u32(const void* p) {
    uint32_t a;
    asm("{ .reg .u64 t; cvta.to.shared.u64 t, %1; cvt.u32.u64 %0, t; }" : "=r"(a) : "l"(p));
    return a;
}
__device__ __forceinline__ void ldsm4(uint32_t* r, uint32_t addr) {
    asm volatile("ldmatrix.sync.aligned.m8n8.x4.shared.b16 {%0,%1,%2,%3}, [%4];"
        : "=r"(r[0]), "=r"(r[1]), "=r"(r[2]), "=r"(r[3]) : "r"(addr));
}
__device__ __forceinline__ void mma16816(float* c, const uint32_t* a, const uint32_t* b) {
    asm volatile("mma.sync.aligned.m16n8k16.row.col.f32.bf16.bf16.f32 "
        "{%0,%1,%2,%3}, {%4,%5,%6,%7}, {%8,%9}, {%0,%1,%2,%3};"
        : "+f"(c[0]), "+f"(c[1]), "+f"(c[2]), "+f"(c[3])
        : "r"(a[0]), "r"(a[1]), "r"(a[2]), "r"(a[3]), "r"(b[0]), "r"(b[1]));
}
__device__ __forceinline__ void cp16(uint32_t smem_addr, const void* gptr) {
    asm volatile("cp.async.cg.shared.global [%0], [%1], 16;"
        :: "r"(smem_addr), "l"(gptr));
}
#define CP_COMMIT() asm volatile("cp.async.commit_group;" ::: "memory")
#define CP_WAIT(n)  asm volatile("cp.async.wait_group %0;" :: "n"(n) : "memory")

// ---------------- generic split-bf16 MMA GEMM: C[M,N] = A@B^T (+b1+b2) ----------------
// CTA tile 128x128, K = kChunks*32. Double-buffered cp.async staging.
#define LSTR 40
#define MAT_B (128 * LSTR * 2)       // bytes per matrix tile (10240)
#define BUF_B (4 * MAT_B)            // bytes per buffer (40960)
#define MMA_SMEM (2 * BUF_B)         // 81920
__global__ __launch_bounds__(256) void mma_nt(
    const bf16* __restrict__ Ah, const bf16* __restrict__ Al,
    const bf16* __restrict__ Bh, const bf16* __restrict__ Bl,
    const float* __restrict__ bias1, const float* __restrict__ bias2,
    float* __restrict__ C, int ldc, int nLimit, int kChunks, int ldA, int ldB,
    bf16* __restrict__ Chi, bf16* __restrict__ Clo)
{
    extern __shared__ char lsm[];
    const uint32_t u0 = smem_u32(lsm);

    const int tid = threadIdx.x;
    const int wid = tid >> 5, lane = tid & 31;
    const int nBase = blockIdx.x * 128;
    const int mBase = blockIdx.y * 128;
    const int wm = (wid & 3) * 32;
    const int wn = (wid >> 2) * 64;

    float acc[2][8][4];
#pragma unroll
    for (int i = 0; i < 2; i++)
#pragma unroll
        for (int j = 0; j < 8; j++)
#pragma unroll
            for (int k = 0; k < 4; k++) acc[i][j][k] = 0.f;

    const int cr = tid >> 1;             // row 0..127
    const int cs = (tid & 1) * 2;        // seg 0 or 2

    const bf16* gsrc[4] = {
        Ah + (size_t)(mBase + cr) * ldA, Al + (size_t)(mBase + cr) * ldA,
        Bh + (size_t)(nBase + cr) * ldB, Bl + (size_t)(nBase + cr) * ldB };
    const uint32_t sdst = u0 + (cr * LSTR + cs * 8) * 2;

    auto stage = [&](int ch, int buf) {
        const int goff = ch * 32 + cs * 8;
#pragma unroll
        for (int m = 0; m < 4; m++) {
            const uint32_t d = sdst + buf * BUF_B + m * MAT_B;
            cp16(d, gsrc[m] + goff);
            cp16(d + 16, gsrc[m] + goff + 8);
        }
        CP_COMMIT();
    };

    stage(0, 0);

    for (int ch = 0; ch < kChunks; ch++) {
        const int cur = ch & 1;
        if (ch + 1 < kChunks) { stage(ch + 1, cur ^ 1); CP_WAIT(1); }
        else                  { CP_WAIT(0); }
        __syncthreads();

        const uint32_t uAh = u0 + cur * BUF_B;
        const uint32_t uAl = uAh + MAT_B;
        const uint32_t uBh = uAl + MAT_B;
        const uint32_t uBl = uBh + MAT_B;

#pragma unroll
        for (int ks = 0; ks < 2; ks++) {
            uint32_t ah[2][4], al[2][4], bh[8][2], bl[8][2];
#pragma unroll
            for (int mt = 0; mt < 2; mt++) {
                const uint32_t off =
                    ((wm + mt * 16 + (lane & 15)) * LSTR + ks * 16 + (lane >> 4) * 8) * 2;
                ldsm4(ah[mt], uAh + off);
                ldsm4(al[mt], uAl + off);
            }
#pragma unroll
            for (int p = 0; p < 4; p++) {
                const uint32_t off =
                    ((wn + p * 16 + ((lane >> 4) & 1) * 8 + (lane & 7)) * LSTR +
                     ks * 16 + ((lane >> 3) & 1) * 8) * 2;
                uint32_t r4[4];
                ldsm4(r4, uBh + off);
                bh[2 * p][0] = r4[0]; bh[2 * p][1] = r4[1];
                bh[2 * p + 1][0] = r4[2]; bh[2 * p + 1][1] = r4[3];
                ldsm4(r4, uBl + off);
                bl[2 * p][0] = r4[0]; bl[2 * p][1] = r4[1];
                bl[2 * p + 1][0] = r4[2]; bl[2 * p + 1][1] = r4[3];
            }
#pragma unroll
            for (int mt = 0; mt < 2; mt++)
#pragma unroll
                for (int nt = 0; nt < 8; nt++) {
                    mma16816(acc[mt][nt], ah[mt], bh[nt]);
                    mma16816(acc[mt][nt], ah[mt], bl[nt]);
                    mma16816(acc[mt][nt], al[mt], bh[nt]);
                }
        }
        __syncthreads();
    }

    const int erow = lane >> 2;
    const int ecol = (lane & 3) * 2;
#pragma unroll
    for (int mt = 0; mt < 2; mt++) {
#pragma unroll
        for (int nt = 0; nt < 8; nt++) {
            const int gn = nBase + wn + nt * 8 + ecol;
            if (gn >= nLimit) continue;
            float b0 = 0.f, b1 = 0.f;
            if (bias1) { b0 += bias1[gn]; b1 += bias1[gn + 1]; }
            if (bias2) { b0 += bias2[gn]; b1 += bias2[gn + 1]; }
            const int r0 = mBase + wm + mt * 16 + erow;
            const float v00 = acc[mt][nt][0] + b0, v01 = acc[mt][nt][1] + b1;
            const float v10 = acc[mt][nt][2] + b0, v11 = acc[mt][nt][3] + b1;
            if (C) {
                *(float2*)&C[(size_t)r0 * ldc + gn] = make_float2(v00, v01);
                *(float2*)&C[(size_t)(r0 + 8) * ldc + gn] = make_float2(v10, v11);
            }
            if (Chi) {
                const size_t i0 = (size_t)r0 * ldc + gn;
                const size_t i1 = (size_t)(r0 + 8) * ldc + gn;
                split_bf16(v00, &Chi[i0], &Clo[i0]);
                split_bf16(v01, &Chi[i0 + 1], &Clo[i0 + 1]);
                split_bf16(v10, &Chi[i1], &Clo[i1]);
                split_bf16(v11, &Chi[i1 + 1], &Clo[i1 + 1]);
            }
        }
    }
}

// ---------------- all input conversions + embedding gather ----------------
#define NB_GATH 8192
#define NB_OUTW 20000
#define NB_PTCH 18816
#define NB_KVW  1536
#define NB_AWK  1024
#define NB_WIH  4096
__global__ void gather_conv(const int* __restrict__ ids, const float* __restrict__ emb,
                            const float* __restrict__ outW, const float* __restrict__ patches,
                            const float* __restrict__ kvW, const float* __restrict__ aWk,
                            const float* __restrict__ Wih)
{
    int blk = blockIdx.x;
    const int tid = threadIdx.x;
    if (blk < NB_GATH) {
        const int i = blk * 256 + tid;
        const int d = i & (DH - 1);
        const int bt = i >> 9;
        split_bf16(emb[(size_t)ids[bt] * DH + d], &g_x_hi[i], &g_x_lo[i]);
        return;
    }
    blk -= NB_GATH;
    if (blk < NB_OUTW) {
        const int j = blk * 256 + tid;
        if (j < VV * DH) split_bf16(outW[j], &g_w_hi[j], &g_w_lo[j]);
        return;
    }
    blk -= NB_OUTW;
    if (blk < NB_PTCH) {
        const int j = blk * 256 + tid;
        split_bf16(patches[j], &g_p_hi[j], &g_p_lo[j]);
        return;
    }
    blk -= NB_PTCH;
    if (blk < NB_KVW) {
        const int j = blk * 256 + tid;
        split_bf16(kvW[j], &g_kvw_hi[j], &g_kvw_lo[j]);
        return;
    }
    blk -= NB_KVW;
    if (blk < NB_AWK) {
        const int j = blk * 256 + tid;
        split_bf16(aWk[j], &g_awk_hi[j], &g_awk_lo[j]);
        return;
    }
    blk -= NB_AWK;
    {
        const int j = blk * 256 + tid;
        const int r = j >> 9, c = j & 511;
        split_bf16(Wih[(size_t)r * 1024 + c], &g_wih_hi[j], &g_wih_lo[j]);
    }
}

// ---------------- persistent decode loop (R9 structure; count-poll barrier) ----------------
__global__ __launch_bounds__(256, 1) void decode_loop(
    const float* __restrict__ Wh, const float* __restrict__ av,
    const float* __restrict__ Wih, const float* __restrict__ Whh,
    const float* __restrict__ lnw, const float* __restrict__ lnb,
    const float* __restrict__ cls,
    const float* __restrict__ ihW, const float* __restrict__ ihb,
    const float* __restrict__ icW, const float* __restrict__ icb)
{
    extern __shared__ float smem[];
    float* wH = smem;                                  // [NH][512]
    float* wX = smem + NH * 512;                       // [NX][512]
    float4* hs4 = (float4*)(smem + (NH + NX) * 512);   // [32][HSTR4]

    __shared__ float s_v[512];
    __shared__ float s_hwh[512];
    __shared__ float s_sc[49];
    __shared__ float s_e[64];
    __shared__ float s_r0[8], s_r1[8], s_mv[2];

    const int tid = threadIdx.x;
    const int bid = blockIdx.x;
    const int warp = tid >> 5, lane = tid & 31;
    const int gwarp = bid * 8 + warp;
    const int b32 = tid & 31, q = tid >> 5;
    unsigned bt = 0;

#pragma unroll
    for (int i = 0; i < NH; i++) {
        const int r = bid * NH + i;
        const float* src = (r < 2048) ? (Whh + (size_t)r * 512)
                          : (r < 2560) ? (Wh + (size_t)(r - 2048) * 512) : nullptr;
        if (src) for (int k = tid; k < 512; k += 256) wH[i * 512 + k] = src[k];
    }
#pragma unroll
    for (int i = 0; i < NX; i++) {
        const int r = bid * NX + i;
        if (r < 2048)
            for (int k = tid; k < 512; k += 256) wX[i * 512 + k] = Wih[(size_t)r * 1024 + 512 + k];
    }
    for (int k = tid; k < 512; k += 256) s_v[k] = av[k];

    // flat barrier: fire-and-forget arrive (RED), poll the count itself
    auto gsync = [&](unsigned target) {
        __syncthreads();
        if (tid == 0) {
            __threadfence();
            atomicAdd(&g_sync[0], 1u);   // return unused -> RED (no round trip)
            while (*(volatile unsigned*)&g_sync[0] < (unsigned)GRID_P * target) {}
            __threadfence();
        }
        __syncthreads();
    };

    // ---- h0/c0 (folded) ----
    for (int j = gwarp; j < 2 * BB * DH; j += GRID_P * 8) {
        const int sel = (j >= BB * DH);
        const int r = sel ? j - BB * DH : j;
        const int b = r >> 9, d = r & (DH - 1);
        const float4* W4 = (const float4*)((sel ? icW : ihW) + (size_t)d * 768);
        const float4* x4 = (const float4*)(cls + (size_t)b * 768);
        float acc = 0.f;
#pragma unroll
        for (int p = 0; p < 6; p++) {
            float4 w = W4[lane + 32 * p];
            float4 x = x4[lane + 32 * p];
            acc += w.x * x.x + w.y * x.y + w.z * x.z + w.w * x.w;
        }
#pragma unroll
        for (int o = 16; o; o >>= 1) acc += __shfl_xor_sync(0xffffffffu, acc, o);
        if (lane == 0) {
            if (sel) g_c[b * DH + d] = acc + icb[d];
            else     g_h[b * DH + d] = acc + ihb[d];
        }
    }
    gsync(++bt);

    for (int t = 0; t < TT; t++) {
        // ======== Phase W: h-gates + hwh (weights in smem) ========
        {
            const float4* hsrc = (const float4*)g_h;
            for (int idx = tid; idx < 32 * 128; idx += 256)
                hs4[(idx >> 7) * HSTR4 + (idx & 127)] = hsrc[idx];
        }
        __syncthreads();
        {
            const float4* hp = hs4 + b32 * HSTR4;
            float4 a0 = make_float4(0.f, 0.f, 0.f, 0.f), a1 = a0, a2 = a0;
            const float4* w0 = (const float4*)(wH + q * 512);
            const float4* w1 = (const float4*)(wH + (q + 8) * 512);
            const float4* w2 = (const float4*)(wH + ((q < 2) ? (q + 16) : 0) * 512);
#pragma unroll 8
            for (int k = 0; k < 128; k++) {
                const float4 h = hp[k];
                const float4 x = w0[k];
                a0.x = fmaf(h.x, x.x, a0.x); a0.y = fmaf(h.y, x.y, a0.y);
                a0.z = fmaf(h.z, x.z, a0.z); a0.w = fmaf(h.w, x.w, a0.w);
                const float4 y = w1[k];
                a1.x = fmaf(h.x, y.x, a1.x); a1.y = fmaf(h.y, y.y, a1.y);
                a1.z = fmaf(h.z, y.z, a1.z); a1.w = fmaf(h.w, y.w, a1.w);
                const float4 z = w2[k];
                a2.x = fmaf(h.x, z.x, a2.x); a2.y = fmaf(h.y, z.y, a2.y);
                a2.z = fmaf(h.z, z.z, a2.z); a2.w = fmaf(h.w, z.w, a2.w);
            }
            const float s0 = (a0.x + a0.y) + (a0.z + a0.w);
            const float s1 = (a1.x + a1.y) + (a1.z + a1.w);
            const float s2 = (a2.x + a2.y) + (a2.z + a2.w);
            int r = bid * NH + q;
            if (r < 2048) g_gh[b32 * 2048 + r] = s0;
            else if (r < 2560) g_hwh[b32 * 512 + r - 2048] = s0;
            r = bid * NH + q + 8;
            if (r < 2048) g_gh[b32 * 2048 + r] = s1;
            else if (r < 2560) g_hwh[b32 * 512 + r - 2048] = s1;
            if (q < 2) {
                r = bid * NH + q + 16;
                if (r < 2048) g_gh[b32 * 2048 + r] = s2;
                else if (r < 2560) g_hwh[b32 * 512 + r - 2048] = s2;
            }
        }
        gsync(++bt);

        // ======== Phase B: chunk scores + partial ctx + per-b combine ========
        if (bid < BB * 4) {
            const int b = bid >> 2, p = bid & 3;
            for (int k = tid; k < 512; k += 256) s_hwh[k] = g_hwh[b * 512 + k];
            __syncthreads();

            for (int n = warp; n < 49; n += 8) {
                const int ng = p * 49 + n;
                const float4* wk4 = (const float4*)(g_wk + ((size_t)(b * NN + ng)) * 512);
                const float4* hw4 = (const float4*)s_hwh;
                const float4* v4  = (const float4*)s_v;
                float s = 0.f;
#pragma unroll
                for (int i = 0; i < 4; i++) {
                    const float4 a = wk4[lane + 32 * i];
                    const float4 c = hw4[lane + 32 * i];
                    const float4 w = v4[lane + 32 * i];
                    s += fast_tanh(a.x + c.x) * w.x + fast_tanh(a.y + c.y) * w.y +
                         fast_tanh(a.z + c.z) * w.z + fast_tanh(a.w + c.w) * w.w;
                }
#pragma unroll
                for (int o = 16; o; o >>= 1) s += __shfl_xor_sync(0xffffffffu, s, o);
                if (lane == 0) s_sc[n] = s;
            }
            __syncthreads();

            if (warp == 0) {
                const float x0 = (lane < 49) ? s_sc[lane] : -1e30f;
                const float x1 = (lane + 32 < 49) ? s_sc[lane + 32] : -1e30f;
                float m = fmaxf(x0, x1);
#pragma unroll
                for (int o = 16; o; o >>= 1) m = fmaxf(m, __shfl_xor_sync(0xffffffffu, m, o));
                const float e0 = (lane < 49) ? __expf(x0 - m) : 0.f;
                const float e1 = (lane + 32 < 49) ? __expf(x1 - m) : 0.f;
                if (lane < 49) s_e[lane] = e0;
                if (lane + 32 < 49) s_e[lane + 32] = e1;
                float su = e0 + e1;
#pragma unroll
                for (int o = 16; o; o >>= 1) su += __shfl_xor_sync(0xffffffffu, su, o);
                if (lane == 0) { g_cm[b * 4 + p] = m; g_cs[b * 4 + p] = su; }
            }
            __syncthreads();

#pragma unroll
            for (int u = 0; u < 2; u++) {
                const int d = tid + 256 * u;
                const float* Kp = g_keys + ((size_t)(b * NN + p * 49)) * 512 + d;
                float a = 0.f;
#pragma unroll 7
                for (int i = 0; i < 49; i++) a = fmaf(s_e[i], Kp[(size_t)i * 512], a);
                g_ctxp[p][b * 512 + d] = a;
            }

            __syncthreads();
            if (tid == 0) {
                __threadfence();
                atomicAdd(&g_sync[2 + b * 32], 1u);
                while (*(volatile unsigned*)&g_sync[2 + b * 32] < 4u * (unsigned)(t + 1)) {}
                __threadfence();
            }
            __syncthreads();

            if (tid < 128) {
                const int d = p * 128 + tid;
                const float m0 = g_cm[b*4+0], m1 = g_cm[b*4+1], m2 = g_cm[b*4+2], m3 = g_cm[b*4+3];
                const float m = fmaxf(fmaxf(m0, m1), fmaxf(m2, m3));
                const float e0 = __expf(m0 - m), e1 = __expf(m1 - m);
                const float e2 = __expf(m2 - m), e3 = __expf(m3 - m);
                const float den = e0 * g_cs[b*4+0] + e1 * g_cs[b*4+1] +
                                  e2 * g_cs[b*4+2] + e3 * g_cs[b*4+3];
                const float v = e0 * g_ctxp[0][b*512+d] + e1 * g_ctxp[1][b*512+d] +
                                e2 * g_ctxp[2][b*512+d] + e3 * g_ctxp[3][b*512+d];
                g_ctx[b * 512 + d] = v / den;
            }
        }
        gsync(++bt);

        // ======== Phase C: ctx-gates (weights in smem) ========
        {
            const float4* csrc = (const float4*)g_ctx;
            for (int idx = tid; idx < 32 * 128; idx += 256)
                hs4[(idx >> 7) * HSTR4 + (idx & 127)] = csrc[idx];
        }
        __syncthreads();
        {
            const float4* cp = hs4 + b32 * HSTR4;
            float4 a0 = make_float4(0.f, 0.f, 0.f, 0.f), a1 = a0;
            const float4* w0 = (const float4*)(wX + q * 512);
            const float4* w1 = (const float4*)(wX + ((q + 8 < NX) ? (q + 8) : 0) * 512);
#pragma unroll 8
            for (int k = 0; k < 128; k++) {
                const float4 h = cp[k];
                const float4 x = w0[k];
                a0.x = fmaf(h.x, x.x, a0.x); a0.y = fmaf(h.y, x.y, a0.y);
                a0.z = fmaf(h.z, x.z, a0.z); a0.w = fmaf(h.w, x.w, a0.w);
                const float4 y = w1[k];
                a1.x = fmaf(h.x, y.x, a1.x); a1.y = fmaf(h.y, y.y, a1.y);
                a1.z = fmaf(h.z, y.z, a1.z); a1.w = fmaf(h.w, y.w, a1.w);
            }
            const float s0 = (a0.x + a0.y) + (a0.z + a0.w);
            const float s1 = (a1.x + a1.y) + (a1.z + a1.w);
            int r = bid * NX + q;
            if (r < 2048) g_gx[b32 * 2048 + r] = s0;
            if (q + 8 < NX) {
                r = bid * NX + q + 8;
                if (r < 2048) g_gx[b32 * 2048 + r] = s1;
            }
        }
        gsync(++bt);

        // ======== Phase D: cell + LayerNorm (32 blocks) ========
        if (bid < BB) {
            const int b = bid;
            const float* Gx = g_Gx + ((size_t)(b * TT + t)) * 2048;
            const float* Gh = g_gh + (size_t)b * 2048;
            const float* Gc = g_gx + (size_t)b * 2048;
            float hr[2];
            float sum = 0.f, ssq = 0.f;
#pragma unroll
            for (int u = 0; u < 2; u++) {
                const int d = tid + 256 * u;
                const float gi = Gx[d]        + Gh[d]        + Gc[d];
                const float gf = Gx[512 + d]  + Gh[512 + d]  + Gc[512 + d];
                const float gg = Gx[1024 + d] + Gh[1024 + d] + Gc[1024 + d];
                const float go = Gx[1536 + d] + Gh[1536 + d] + Gc[1536 + d];
                const float c_old = g_c[b * DH + d];
                const float cn = sigm(gf) * c_old + sigm(gi) * tanhf(gg);
                g_c[b * DH + d] = cn;
                const float h = sigm(go) * tanhf(cn);
                hr[u] = h; sum += h; ssq += h * h;
            }
#pragma unroll
            for (int o = 16; o; o >>= 1) {
                sum += __shfl_xor_sync(0xffffffffu, sum, o);
                ssq += __shfl_xor_sync(0xffffffffu, ssq, o);
            }
            if (lane == 0) { s_r0[warp] = sum; s_r1[warp] = ssq; }
            __syncthreads();
            if (tid < 8) {
                float s = s_r0[tid], qq = s_r1[tid];
#pragma unroll
                for (int o = 4; o; o >>= 1) {
                    s += __shfl_xor_sync(0x000000ffu, s, o);
                    qq += __shfl_xor_sync(0x000000ffu, qq, o);
                }
                if (tid == 0) { s_mv[0] = s * (1.f / DH); s_mv[1] = qq * (1.f / DH); }
            }
            __syncthreads();
            const float mu = s_mv[0];
            const float var = s_mv[1] - mu * mu;
            const float rstd = rsqrtf(var + 1e-5f);
#pragma unroll
            for (int u = 0; u < 2; u++) {
                const int d = tid + 256 * u;
                const float h = (hr[u] - mu) * rstd * lnw[d] + lnb[d];
                g_h[b * DH + d] = h;
                const size_t idx = ((size_t)(b * TT + t)) * DH + d;
                split_bf16(h, &g_hall_hi[idx], &g_hall_lo[idx]);
            }
        }
        gsync(++bt);
    }
}

// ---------------- launch ----------------
extern "C" void kernel_launch(void* const* d_in, const int* in_sizes, int n_in,
                              void* d_out, int out_size)
{
    const float* patches = (const float*)d_in[0];
    const float* cls     = (const float*)d_in[1];
    const int*   tgt     = (const int*)  d_in[2];
    const float* emb     = (const float*)d_in[3];
    const float* kvW     = (const float*)d_in[4];
    const float* kvb     = (const float*)d_in[5];
    const float* ihW     = (const float*)d_in[6];
    const float* ihb     = (const float*)d_in[7];
    const float* icW     = (const float*)d_in[8];
    const float* icb     = (const float*)d_in[9];
    const float* aWh     = (const float*)d_in[10];
    const float* aWk     = (const float*)d_in[11];
    const float* av      = (const float*)d_in[12];
    const float* Wih     = (const float*)d_in[13];
    const float* Whh     = (const float*)d_in[14];
    const float* bih     = (const float*)d_in[15];
    const float* bhh     = (const float*)d_in[16];
    const float* lnw     = (const float*)d_in[17];
    const float* lnb     = (const float*)d_in[18];
    const float* outW    = (const float*)d_in[19];
    const float* outb    = (const float*)d_in[20];
    float* out = (float*)d_out;

    float *keys, *wk, *Gx;
    bf16 *xh, *xl, *ph, *pl, *kvh, *kvl, *awh, *awl, *wih_h, *wih_l;
    bf16 *kh, *kl, *hh, *hl, *wh, *wl;
    unsigned* syncp;
    cudaGetSymbolAddress((void**)&keys, g_keys);
    cudaGetSymbolAddress((void**)&wk,   g_wk);
    cudaGetSymbolAddress((void**)&Gx,   g_Gx);
    cudaGetSymbolAddress((void**)&syncp, g_sync);
    cudaGetSymbolAddress((void**)&xh, g_x_hi);   cudaGetSymbolAddress((void**)&xl, g_x_lo);
    cudaGetSymbolAddress((void**)&ph, g_p_hi);   cudaGetSymbolAddress((void**)&pl, g_p_lo);
    cudaGetSymbolAddress((void**)&kvh, g_kvw_hi); cudaGetSymbolAddress((void**)&kvl, g_kvw_lo);
    cudaGetSymbolAddress((void**)&awh, g_awk_hi); cudaGetSymbolAddress((void**)&awl, g_awk_lo);
    cudaGetSymbolAddress((void**)&wih_h, g_wih_hi); cudaGetSymbolAddress((void**)&wih_l, g_wih_lo);
    cudaGetSymbolAddress((void**)&kh, g_keys_hi); cudaGetSymbolAddress((void**)&kl, g_keys_lo);
    cudaGetSymbolAddress((void**)&hh, g_hall_hi); cudaGetSymbolAddress((void**)&hl, g_hall_lo);
    cudaGetSymbolAddress((void**)&wh, g_w_hi);    cudaGetSymbolAddress((void**)&wl, g_w_lo);

    cudaMemsetAsync(syncp, 0, (2 + BB * 32) * sizeof(unsigned));

    cudaFuncSetAttribute(decode_loop, cudaFuncAttributeMaxDynamicSharedMemorySize,
                         DYN_FLOATS * (int)sizeof(float));
    cudaFuncSetAttribute(mma_nt, cudaFuncAttributeMaxDynamicSharedMemorySize, MMA_SMEM);

    gather_conv<<<NB_GATH + NB_OUTW + NB_PTCH + NB_KVW + NB_AWK + NB_WIH, 256>>>(
        tgt, emb, outW, patches, kvW, aWk, Wih);

    // keys = patches @ kvW^T + kvb     [6272 x 512], K=768 (also emit bf16 split)
    mma_nt<<<dim3(4, 49), 256, MMA_SMEM>>>(ph, pl, kvh, kvl, kvb, nullptr,
                                           keys, 512, 512, 24, 768, 768, kh, kl);
    // wk = keys @ aWk^T                [6272 x 512], K=512
    mma_nt<<<dim3(4, 49), 256, MMA_SMEM>>>(kh, kl, awh, awl, nullptr, nullptr,
                                           wk, 512, 512, 16, 512, 512, nullptr, nullptr);
    // Gx = x @ Wih_x^T + b_ih + b_hh   [4096 x 2048], K=512
    mma_nt<<<dim3(16, 32), 256, MMA_SMEM>>>(xh, xl, wih_h, wih_l, bih, bhh,
                                            Gx, 2048, 2048, 16, 512, 512, nullptr, nullptr);

    decode_loop<<<GRID_P, 256, DYN_FLOATS * sizeof(float)>>>(
        aWh, av, Wih, Whh, lnw, lnb, cls, ihW, ihb, icW, icb);

    // logits = hall @ outW^T + outb    [4096 x 10000], K=512
    mma_nt<<<dim3(79, 32), 256, MMA_SMEM>>>(hh, hl, wh, wl, outb, nullptr,
                                            out, VV, VV, 16, 512, 512, nullptr, nullptr);
}

// round 14
// speedup vs baseline: 1.1499x; 1.0963x over previous
#include <cuda_runtime.h>
#include <cuda_bf16.h>
#include <math.h>
#include <stdint.h>

#define BB 32
#define NN 196
#define TT 128
#define DH 512
#define VV 10000
#define VPAD 10112
#define GRID_P 148
#define NH 18              // bankH rows/CTA: Whh(2048)+Wh(512)=2560 <= 148*18
#define NX 14              // bankX rows/CTA: Wih ctx cols 2048 <= 148*14
#define HSTR4 129          // float4 stride of h_s rows (516 floats, conflict-free)
#define DYN_FLOATS ((NH + NX) * 512 + 32 * 516)

typedef __nv_bfloat16 bf16;

// ---------------- device scratch (static, no allocation) ----------------
__device__ float g_keys[BB * NN * DH];
__device__ float g_wk  [BB * NN * DH];
__device__ float g_Gx  [BB * TT * 4 * DH];
__device__ float g_h   [BB * DH];
__device__ float g_c   [BB * DH];
__device__ float g_hwh [BB * DH];
__device__ float g_gh  [BB * 4 * DH];
__device__ float g_gx  [BB * 4 * DH];
__device__ float g_ctx [BB * DH];
__device__ float g_ctxp[4][BB * DH];
__device__ float g_cm[BB * 4], g_cs[BB * 4];
__device__ unsigned g_sync[2 + BB * 32];     // [0]=count [2+b*32]=mini-barriers
__device__ bf16 g_hall_hi[BB * TT * DH], g_hall_lo[BB * TT * DH];
__device__ bf16 g_w_hi[VPAD * DH], g_w_lo[VPAD * DH];   // rows >= VV stay zero
__device__ bf16 g_x_hi[BB * TT * DH], g_x_lo[BB * TT * DH];
__device__ bf16 g_p_hi[BB * NN * 768], g_p_lo[BB * NN * 768];
__device__ bf16 g_kvw_hi[512 * 768], g_kvw_lo[512 * 768];
__device__ bf16 g_awk_hi[512 * 512], g_awk_lo[512 * 512];
__device__ bf16 g_wih_hi[2048 * 512], g_wih_lo[2048 * 512];
__device__ bf16 g_keys_hi[BB * NN * DH], g_keys_lo[BB * NN * DH];

__device__ __forceinline__ float fast_tanh(float x) {
    float y; asm("tanh.approx.f32 %0, %1;" : "=f"(y) : "f"(x)); return y;
}
__device__ __forceinline__ float sigm(float x) { return 1.f / (1.f + expf(-x)); }
__device__ __forceinline__ void split_bf16(float v, bf16* hi, bf16* lo) {
    const bf16 h = __float2bfloat16(v);
    *hi = h;
    *lo = __float2bfloat16(v - __bfloat162float(h));
}

// release-arrive / acquire-poll primitives (no full membar on critical path)
__device__ __forceinline__ void red_release_add(unsigned* p) {
    asm volatile("red.release.gpu.global.add.u32 [%0], %1;" :: "l"(p), "r"(1u) : "memory");
}
__device__ __forceinline__ unsigned ld_acquire(const unsigned* p) {
    unsigned v;
    asm volatile("ld.acquire.gpu.global.u32 %0, [%1];" : "=r"(v) : "l"(p) : "memory");
    return v;
}

// ---------------- mma.sync helpers (sm_80 PTX — valid at compute_103) ----------------
__device__ __forceinline__ uint32_t smem_u32(const void* p) {
    uint32_t a;
    asm("{ .reg .u64 t; cvta.to.shared.u64 t, %1; cvt.u32.u64 %0, t; }" : "=r"(a) : "l"(p));
    return a;
}
__device__ __forceinline__ void ldsm4(uint32_t* r, uint32_t addr) {
    asm volatile("ldmatrix.sync.aligned.m8n8.x4.shared.b16 {%0,%1,%2,%3}, [%4];"
        : "=r"(r[0]), "=r"(r[1]), "=r"(r[2]), "=r"(r[3]) : "r"(addr));
}
__device__ __forceinline__ void mma16816(float* c, const uint32_t* a, const uint32_t* b) {
    asm volatile("mma.sync.aligned.m16n8k16.row.col.f32.bf16.bf16.f32 "
        "{%0,%1,%2,%3}, {%4,%5,%6,%7}, {%8,%9}, {%0,%1,%2,%3};"
        : "+f"(c[0]), "+f"(c[1]), "+f"(c[2]), "+f"(c[3])
        : "r"(a[0]), "r"(a[1]), "r"(a[2]), "r"(a[3]), "r"(b[0]), "r"(b[1]));
}
__device__ __forceinline__ void cp16(uint32_t smem_addr, const void* gptr) {
    asm volatile("cp.async.cg.shared.global [%0], [%1], 16;"
        :: "r"(smem_addr), "l"(gptr));
}
#define CP_COMMIT() asm volatile("cp.async.commit_group;" ::: "memory")
#define CP_WAIT(n)  asm volatile("cp.async.wait_group %0;" :: "n"(n) : "memory")

// ---------------- generic split-bf16 MMA GEMM: C[M,N] = A@B^T (+b1+b2) ----------------
// CTA tile 128x128, K = kChunks*32. Double-buffered cp.async staging, 2 CTA/SM.
#define LSTR 40
#define MAT_B (128 * LSTR * 2)       // bytes per matrix tile (10240)
#define BUF_B (4 * MAT_B)            // bytes per buffer (40960)
#define MMA_SMEM (2 * BUF_B)         // 81920
__global__ __launch_bounds__(256, 2) void mma_nt(
    const bf16* __restrict__ Ah, const bf16* __restrict__ Al,
    const bf16* __restrict__ Bh, const bf16* __restrict__ Bl,
    const float* __restrict__ bias1, const float* __restrict__ bias2,
    float* __restrict__ C, int ldc, int nLimit, int kChunks, int ldA, int ldB,
    bf16* __restrict__ Chi, bf16* __restrict__ Clo)
{
    extern __shared__ char lsm[];
    const uint32_t u0 = smem_u32(lsm);

    const int tid = threadIdx.x;
    const int wid = tid >> 5, lane = tid & 31;
    const int nBase = blockIdx.x * 128;
    const int mBase = blockIdx.y * 128;
    const int wm = (wid & 3) * 32;
    const int wn = (wid >> 2) * 64;

    float acc[2][8][4];
#pragma unroll
    for (int i = 0; i < 2; i++)
#pragma unroll
        for (int j = 0; j < 8; j++)
#pragma unroll
            for (int k = 0; k < 4; k++) acc[i][j][k] = 0.f;

    const int cr = tid >> 1;             // row 0..127
    const int cs = (tid & 1) * 2;        // seg 0 or 2

    const bf16* gsrc[4] = {
        Ah + (size_t)(mBase + cr) * ldA, Al + (size_t)(mBase + cr) * ldA,
        Bh + (size_t)(nBase + cr) * ldB, Bl + (size_t)(nBase + cr) * ldB };
    const uint32_t sdst = u0 + (cr * LSTR + cs * 8) * 2;

    auto stage = [&](int ch, int buf) {
        const int goff = ch * 32 + cs * 8;
#pragma unroll
        for (int m = 0; m < 4; m++) {
            const uint32_t d = sdst + buf * BUF_B + m * MAT_B;
            cp16(d, gsrc[m] + goff);
            cp16(d + 16, gsrc[m] + goff + 8);
        }
        CP_COMMIT();
    };

    stage(0, 0);

    for (int ch = 0; ch < kChunks; ch++) {
        const int cur = ch & 1;
        if (ch + 1 < kChunks) { stage(ch + 1, cur ^ 1); CP_WAIT(1); }
        else                  { CP_WAIT(0); }
        __syncthreads();

        const uint32_t uAh = u0 + cur * BUF_B;
        const uint32_t uAl = uAh + MAT_B;
        const uint32_t uBh = uAl + MAT_B;
        const uint32_t uBl = uBh + MAT_B;

#pragma unroll
        for (int ks = 0; ks < 2; ks++) {
            uint32_t ah[2][4], al[2][4], bh[8][2], bl[8][2];
#pragma unroll
            for (int mt = 0; mt < 2; mt++) {
                const uint32_t off =
                    ((wm + mt * 16 + (lane & 15)) * LSTR + ks * 16 + (lane >> 4) * 8) * 2;
                ldsm4(ah[mt], uAh + off);
                ldsm4(al[mt], uAl + off);
            }
#pragma unroll
            for (int p = 0; p < 4; p++) {
                const uint32_t off =
                    ((wn + p * 16 + ((lane >> 4) & 1) * 8 + (lane & 7)) * LSTR +
                     ks * 16 + ((lane >> 3) & 1) * 8) * 2;
                uint32_t r4[4];
                ldsm4(r4, uBh + off);
                bh[2 * p][0] = r4[0]; bh[2 * p][1] = r4[1];
                bh[2 * p + 1][0] = r4[2]; bh[2 * p + 1][1] = r4[3];
                ldsm4(r4, uBl + off);
                bl[2 * p][0] = r4[0]; bl[2 * p][1] = r4[1];
                bl[2 * p + 1][0] = r4[2]; bl[2 * p + 1][1] = r4[3];
            }
#pragma unroll
            for (int mt = 0; mt < 2; mt++)
#pragma unroll
                for (int nt = 0; nt < 8; nt++) {
                    mma16816(acc[mt][nt], ah[mt], bh[nt]);
                    mma16816(acc[mt][nt], ah[mt], bl[nt]);
                    mma16816(acc[mt][nt], al[mt], bh[nt]);
                }
        }
        __syncthreads();
    }

    const int erow = lane >> 2;
    const int ecol = (lane & 3) * 2;
#pragma unroll
    for (int mt = 0; mt < 2; mt++) {
#pragma unroll
        for (int nt = 0; nt < 8; nt++) {
            const int gn = nBase + wn + nt * 8 + ecol;
            if (gn >= nLimit) continue;
            float b0 = 0.f, b1 = 0.f;
            if (bias1) { b0 += bias1[gn]; b1 += bias1[gn + 1]; }
            if (bias2) { b0 += bias2[gn]; b1 += bias2[gn + 1]; }
            const int r0 = mBase + wm + mt * 16 + erow;
            const float v00 = acc[mt][nt][0] + b0, v01 = acc[mt][nt][1] + b1;
            const float v10 = acc[mt][nt][2] + b0, v11 = acc[mt][nt][3] + b1;
            if (C) {
                *(float2*)&C[(size_t)r0 * ldc + gn] = make_float2(v00, v01);
                *(float2*)&C[(size_t)(r0 + 8) * ldc + gn] = make_float2(v10, v11);
            }
            if (Chi) {
                const size_t i0 = (size_t)r0 * ldc + gn;
                const size_t i1 = (size_t)(r0 + 8) * ldc + gn;
                split_bf16(v00, &Chi[i0], &Clo[i0]);
                split_bf16(v01, &Chi[i0 + 1], &Clo[i0 + 1]);
                split_bf16(v10, &Chi[i1], &Clo[i1]);
                split_bf16(v11, &Chi[i1 + 1], &Clo[i1 + 1]);
            }
        }
    }
}

// ---------------- all input conversions + embedding gather ----------------
#define NB_GATH 8192
#define NB_OUTW 20000
#define NB_PTCH 18816
#define NB_KVW  1536
#define NB_AWK  1024
#define NB_WIH  4096
__global__ void gather_conv(const int* __restrict__ ids, const float* __restrict__ emb,
                            const float* __restrict__ outW, const float* __restrict__ patches,
                            const float* __restrict__ kvW, const float* __restrict__ aWk,
                            const float* __restrict__ Wih)
{
    int blk = blockIdx.x;
    const int tid = threadIdx.x;
    if (blk < NB_GATH) {
        const int i = blk * 256 + tid;
        const int d = i & (DH - 1);
        const int bt = i >> 9;
        split_bf16(emb[(size_t)ids[bt] * DH + d], &g_x_hi[i], &g_x_lo[i]);
        return;
    }
    blk -= NB_GATH;
    if (blk < NB_OUTW) {
        const int j = blk * 256 + tid;
        if (j < VV * DH) split_bf16(outW[j], &g_w_hi[j], &g_w_lo[j]);
        return;
    }
    blk -= NB_OUTW;
    if (blk < NB_PTCH) {
        const int j = blk * 256 + tid;
        split_bf16(patches[j], &g_p_hi[j], &g_p_lo[j]);
        return;
    }
    blk -= NB_PTCH;
    if (blk < NB_KVW) {
        const int j = blk * 256 + tid;
        split_bf16(kvW[j], &g_kvw_hi[j], &g_kvw_lo[j]);
        return;
    }
    blk -= NB_KVW;
    if (blk < NB_AWK) {
        const int j = blk * 256 + tid;
        split_bf16(aWk[j], &g_awk_hi[j], &g_awk_lo[j]);
        return;
    }
    blk -= NB_AWK;
    {
        const int j = blk * 256 + tid;
        const int r = j >> 9, c = j & 511;
        split_bf16(Wih[(size_t)r * 1024 + c], &g_wih_hi[j], &g_wih_lo[j]);
    }
}

// ---------------- persistent decode loop (count-poll barrier, acq/rel) ----------------
__global__ __launch_bounds__(256, 1) void decode_loop(
    const float* __restrict__ Wh, const float* __restrict__ av,
    const float* __restrict__ Wih, const float* __restrict__ Whh,
    const float* __restrict__ lnw, const float* __restrict__ lnb,
    const float* __restrict__ cls,
    const float* __restrict__ ihW, const float* __restrict__ ihb,
    const float* __restrict__ icW, const float* __restrict__ icb)
{
    extern __shared__ float smem[];
    float* wH = smem;                                  // [NH][512]
    float* wX = smem + NH * 512;                       // [NX][512]
    float4* hs4 = (float4*)(smem + (NH + NX) * 512);   // [32][HSTR4]

    __shared__ float s_v[512];
    __shared__ float s_hwh[512];
    __shared__ float s_sc[49];
    __shared__ float s_e[64];
    __shared__ float s_r0[8], s_r1[8], s_mv[2];

    const int tid = threadIdx.x;
    const int bid = blockIdx.x;
    const int warp = tid >> 5, lane = tid & 31;
    const int gwarp = bid * 8 + warp;
    const int b32 = tid & 31, q = tid >> 5;
    unsigned bt = 0;

#pragma unroll
    for (int i = 0; i < NH; i++) {
        const int r = bid * NH + i;
        const float* src = (r < 2048) ? (Whh + (size_t)r * 512)
                          : (r < 2560) ? (Wh + (size_t)(r - 2048) * 512) : nullptr;
        if (src) for (int k = tid; k < 512; k += 256) wH[i * 512 + k] = src[k];
    }
#pragma unroll
    for (int i = 0; i < NX; i++) {
        const int r = bid * NX + i;
        if (r < 2048)
            for (int k = tid; k < 512; k += 256) wX[i * 512 + k] = Wih[(size_t)r * 1024 + 512 + k];
    }
    for (int k = tid; k < 512; k += 256) s_v[k] = av[k];

    // flat barrier: release-arrive (RED), acquire-poll the count itself
    auto gsync = [&](unsigned target) {
        __syncthreads();
        if (tid == 0) {
            red_release_add(&g_sync[0]);
            while (ld_acquire(&g_sync[0]) < (unsigned)GRID_P * target) { __nanosleep(20); }
        }
        __syncthreads();
    };

    // ---- h0/c0 (folded) ----
    for (int j = gwarp; j < 2 * BB * DH; j += GRID_P * 8) {
        const int sel = (j >= BB * DH);
        const int r = sel ? j - BB * DH : j;
        const int b = r >> 9, d = r & (DH - 1);
        const float4* W4 = (const float4*)((sel ? icW : ihW) + (size_t)d * 768);
        const float4* x4 = (const float4*)(cls + (size_t)b * 768);
        float acc = 0.f;
#pragma unroll
        for (int p = 0; p < 6; p++) {
            float4 w = W4[lane + 32 * p];
            float4 x = x4[lane + 32 * p];
            acc += w.x * x.x + w.y * x.y + w.z * x.z + w.w * x.w;
        }
#pragma unroll
        for (int o = 16; o; o >>= 1) acc += __shfl_xor_sync(0xffffffffu, acc, o);
        if (lane == 0) {
            if (sel) g_c[b * DH + d] = acc + icb[d];
            else     g_h[b * DH + d] = acc + ihb[d];
        }
    }
    gsync(++bt);

    for (int t = 0; t < TT; t++) {
        // ======== Phase W: h-gates + hwh (weights in smem) ========
        {
            const float4* hsrc = (const float4*)g_h;
            for (int idx = tid; idx < 32 * 128; idx += 256)
                hs4[(idx >> 7) * HSTR4 + (idx & 127)] = hsrc[idx];
        }
        __syncthreads();
        {
            const float4* hp = hs4 + b32 * HSTR4;
            float4 a0 = make_float4(0.f, 0.f, 0.f, 0.f), a1 = a0, a2 = a0;
            const float4* w0 = (const float4*)(wH + q * 512);
            const float4* w1 = (const float4*)(wH + (q + 8) * 512);
            const float4* w2 = (const float4*)(wH + ((q < 2) ? (q + 16) : 0) * 512);
#pragma unroll 8
            for (int k = 0; k < 128; k++) {
                const float4 h = hp[k];
                const float4 x = w0[k];
                a0.x = fmaf(h.x, x.x, a0.x); a0.y = fmaf(h.y, x.y, a0.y);
                a0.z = fmaf(h.z, x.z, a0.z); a0.w = fmaf(h.w, x.w, a0.w);
                const float4 y = w1[k];
                a1.x = fmaf(h.x, y.x, a1.x); a1.y = fmaf(h.y, y.y, a1.y);
                a1.z = fmaf(h.z, y.z, a1.z); a1.w = fmaf(h.w, y.w, a1.w);
                const float4 z = w2[k];
                a2.x = fmaf(h.x, z.x, a2.x); a2.y = fmaf(h.y, z.y, a2.y);
                a2.z = fmaf(h.z, z.z, a2.z); a2.w = fmaf(h.w, z.w, a2.w);
            }
            const float s0 = (a0.x + a0.y) + (a0.z + a0.w);
            const float s1 = (a1.x + a1.y) + (a1.z + a1.w);
            const float s2 = (a2.x + a2.y) + (a2.z + a2.w);
            int r = bid * NH + q;
            if (r < 2048) g_gh[b32 * 2048 + r] = s0;
            else if (r < 2560) g_hwh[b32 * 512 + r - 2048] = s0;
            r = bid * NH + q + 8;
            if (r < 2048) g_gh[b32 * 2048 + r] = s1;
            else if (r < 2560) g_hwh[b32 * 512 + r - 2048] = s1;
            if (q < 2) {
                r = bid * NH + q + 16;
                if (r < 2048) g_gh[b32 * 2048 + r] = s2;
                else if (r < 2560) g_hwh[b32 * 512 + r - 2048] = s2;
            }
        }
        gsync(++bt);

        // ======== Phase B: chunk scores + partial ctx + per-b combine ========
        if (bid < BB * 4) {
            const int b = bid >> 2, p = bid & 3;
            for (int k = tid; k < 512; k += 256) s_hwh[k] = g_hwh[b * 512 + k];
            __syncthreads();

            for (int n = warp; n < 49; n += 8) {
                const int ng = p * 49 + n;
                const float4* wk4 = (const float4*)(g_wk + ((size_t)(b * NN + ng)) * 512);
                const float4* hw4 = (const float4*)s_hwh;
                const float4* v4  = (const float4*)s_v;
                float s = 0.f;
#pragma unroll
                for (int i = 0; i < 4; i++) {
                    const float4 a = wk4[lane + 32 * i];
                    const float4 c = hw4[lane + 32 * i];
                    const float4 w = v4[lane + 32 * i];
                    s += fast_tanh(a.x + c.x) * w.x + fast_tanh(a.y + c.y) * w.y +
                         fast_tanh(a.z + c.z) * w.z + fast_tanh(a.w + c.w) * w.w;
                }
#pragma unroll
                for (int o = 16; o; o >>= 1) s += __shfl_xor_sync(0xffffffffu, s, o);
                if (lane == 0) s_sc[n] = s;
            }
            __syncthreads();

            if (warp == 0) {
                const float x0 = (lane < 49) ? s_sc[lane] : -1e30f;
                const float x1 = (lane + 32 < 49) ? s_sc[lane + 32] : -1e30f;
                float m = fmaxf(x0, x1);
#pragma unroll
                for (int o = 16; o; o >>= 1) m = fmaxf(m, __shfl_xor_sync(0xffffffffu, m, o));
                const float e0 = (lane < 49) ? __expf(x0 - m) : 0.f;
                const float e1 = (lane + 32 < 49) ? __expf(x1 - m) : 0.f;
                if (lane < 49) s_e[lane] = e0;
                if (lane + 32 < 49) s_e[lane + 32] = e1;
                float su = e0 + e1;
#pragma unroll
                for (int o = 16; o; o >>= 1) su += __shfl_xor_sync(0xffffffffu, su, o);
                if (lane == 0) { g_cm[b * 4 + p] = m; g_cs[b * 4 + p] = su; }
            }
            __syncthreads();

#pragma unroll
            for (int u = 0; u < 2; u++) {
                const int d = tid + 256 * u;
                const float* Kp = g_keys + ((size_t)(b * NN + p * 49)) * 512 + d;
                float a = 0.f;
#pragma unroll 7
                for (int i = 0; i < 49; i++) a = fmaf(s_e[i], Kp[(size_t)i * 512], a);
                g_ctxp[p][b * 512 + d] = a;
            }

            __syncthreads();
            if (tid == 0) {
                red_release_add(&g_sync[2 + b * 32]);
                while (ld_acquire(&g_sync[2 + b * 32]) < 4u * (unsigned)(t + 1)) { __nanosleep(20); }
            }
            __syncthreads();

            if (tid < 128) {
                const int d = p * 128 + tid;
                const float m0 = g_cm[b*4+0], m1 = g_cm[b*4+1], m2 = g_cm[b*4+2], m3 = g_cm[b*4+3];
                const float m = fmaxf(fmaxf(m0, m1), fmaxf(m2, m3));
                const float e0 = __expf(m0 - m), e1 = __expf(m1 - m);
                const float e2 = __expf(m2 - m), e3 = __expf(m3 - m);
                const float den = e0 * g_cs[b*4+0] + e1 * g_cs[b*4+1] +
                                  e2 * g_cs[b*4+2] + e3 * g_cs[b*4+3];
                const float v = e0 * g_ctxp[0][b*512+d] + e1 * g_ctxp[1][b*512+d] +
                                e2 * g_ctxp[2][b*512+d] + e3 * g_ctxp[3][b*512+d];
                g_ctx[b * 512 + d] = v / den;
            }
        }
        gsync(++bt);

        // ======== Phase C: ctx-gates (weights in smem) ========
        {
            const float4* csrc = (const float4*)g_ctx;
            for (int idx = tid; idx < 32 * 128; idx += 256)
                hs4[(idx >> 7) * HSTR4 + (idx & 127)] = csrc[idx];
        }
        __syncthreads();
        {
            const float4* cp = hs4 + b32 * HSTR4;
            float4 a0 = make_float4(0.f, 0.f, 0.f, 0.f), a1 = a0;
            const float4* w0 = (const float4*)(wX + q * 512);
            const float4* w1 = (const float4*)(wX + ((q + 8 < NX) ? (q + 8) : 0) * 512);
#pragma unroll 8
            for (int k = 0; k < 128; k++) {
                const float4 h = cp[k];
                const float4 x = w0[k];
                a0.x = fmaf(h.x, x.x, a0.x); a0.y = fmaf(h.y, x.y, a0.y);
                a0.z = fmaf(h.z, x.z, a0.z); a0.w = fmaf(h.w, x.w, a0.w);
                const float4 y = w1[k];
                a1.x = fmaf(h.x, y.x, a1.x); a1.y = fmaf(h.y, y.y, a1.y);
                a1.z = fmaf(h.z, y.z, a1.z); a1.w = fmaf(h.w, y.w, a1.w);
            }
            const float s0 = (a0.x + a0.y) + (a0.z + a0.w);
            const float s1 = (a1.x + a1.y) + (a1.z + a1.w);
            int r = bid * NX + q;
            if (r < 2048) g_gx[b32 * 2048 + r] = s0;
            if (q + 8 < NX) {
                r = bid * NX + q + 8;
                if (r < 2048) g_gx[b32 * 2048 + r] = s1;
            }
        }
        gsync(++bt);

        // ======== Phase D: cell + LayerNorm (32 blocks) ========
        if (bid < BB) {
            const int b = bid;
            const float* Gx = g_Gx + ((size_t)(b * TT + t)) * 2048;
            const float* Gh = g_gh + (size_t)b * 2048;
            const float* Gc = g_gx + (size_t)b * 2048;
            float hr[2];
            float sum = 0.f, ssq = 0.f;
#pragma unroll
            for (int u = 0; u < 2; u++) {
                const int d = tid + 256 * u;
                const float gi = Gx[d]        + Gh[d]        + Gc[d];
                const float gf = Gx[512 + d]  + Gh[512 + d]  + Gc[512 + d];
                const float gg = Gx[1024 + d] + Gh[1024 + d] + Gc[1024 + d];
                const float go = Gx[1536 + d] + Gh[1536 + d] + Gc[1536 + d];
                const float c_old = g_c[b * DH + d];
                const float cn = sigm(gf) * c_old + sigm(gi) * tanhf(gg);
                g_c[b * DH + d] = cn;
                const float h = sigm(go) * tanhf(cn);
                hr[u] = h; sum += h; ssq += h * h;
            }
#pragma unroll
            for (int o = 16; o; o >>= 1) {
                sum += __shfl_xor_sync(0xffffffffu, sum, o);
                ssq += __shfl_xor_sync(0xffffffffu, ssq, o);
            }
            if (lane == 0) { s_r0[warp] = sum; s_r1[warp] = ssq; }
            __syncthreads();
            if (tid < 8) {
                float s = s_r0[tid], qq = s_r1[tid];
#pragma unroll
                for (int o = 4; o; o >>= 1) {
                    s += __shfl_xor_sync(0x000000ffu, s, o);
                    qq += __shfl_xor_sync(0x000000ffu, qq, o);
                }
                if (tid == 0) { s_mv[0] = s * (1.f / DH); s_mv[1] = qq * (1.f / DH); }
            }
            __syncthreads();
            const float mu = s_mv[0];
            const float var = s_mv[1] - mu * mu;
            const float rstd = rsqrtf(var + 1e-5f);
#pragma unroll
            for (int u = 0; u < 2; u++) {
                const int d = tid + 256 * u;
                const float h = (hr[u] - mu) * rstd * lnw[d] + lnb[d];
                g_h[b * DH + d] = h;
                const size_t idx = ((size_t)(b * TT + t)) * DH + d;
                split_bf16(h, &g_hall_hi[idx], &g_hall_lo[idx]);
            }
        }
        gsync(++bt);
    }
}

// ---------------- launch ----------------
extern "C" void kernel_launch(void* const* d_in, const int* in_sizes, int n_in,
                              void* d_out, int out_size)
{
    const float* patches = (const float*)d_in[0];
    const float* cls     = (const float*)d_in[1];
    const int*   tgt     = (const int*)  d_in[2];
    const float* emb     = (const float*)d_in[3];
    const float* kvW     = (const float*)d_in[4];
    const float* kvb     = (const float*)d_in[5];
    const float* ihW     = (const float*)d_in[6];
    const float* ihb     = (const float*)d_in[7];
    const float* icW     = (const float*)d_in[8];
    const float* icb     = (const float*)d_in[9];
    const float* aWh     = (const float*)d_in[10];
    const float* aWk     = (const float*)d_in[11];
    const float* av      = (const float*)d_in[12];
    const float* Wih     = (const float*)d_in[13];
    const float* Whh     = (const float*)d_in[14];
    const float* bih     = (const float*)d_in[15];
    const float* bhh     = (const float*)d_in[16];
    const float* lnw     = (const float*)d_in[17];
    const float* lnb     = (const float*)d_in[18];
    const float* outW    = (const float*)d_in[19];
    const float* outb    = (const float*)d_in[20];
    float* out = (float*)d_out;

    float *keys, *wk, *Gx;
    bf16 *xh, *xl, *ph, *pl, *kvh, *kvl, *awh, *awl, *wih_h, *wih_l;
    bf16 *kh, *kl, *hh, *hl, *wh, *wl;
    unsigned* syncp;
    cudaGetSymbolAddress((void**)&keys, g_keys);
    cudaGetSymbolAddress((void**)&wk,   g_wk);
    cudaGetSymbolAddress((void**)&Gx,   g_Gx);
    cudaGetSymbolAddress((void**)&syncp, g_sync);
    cudaGetSymbolAddress((void**)&xh, g_x_hi);   cudaGetSymbolAddress((void**)&xl, g_x_lo);
    cudaGetSymbolAddress((void**)&ph, g_p_hi);   cudaGetSymbolAddress((void**)&pl, g_p_lo);
    cudaGetSymbolAddress((void**)&kvh, g_kvw_hi); cudaGetSymbolAddress((void**)&kvl, g_kvw_lo);
    cudaGetSymbolAddress((void**)&awh, g_awk_hi); cudaGetSymbolAddress((void**)&awl, g_awk_lo);
    cudaGetSymbolAddress((void**)&wih_h, g_wih_hi); cudaGetSymbolAddress((void**)&wih_l, g_wih_lo);
    cudaGetSymbolAddress((void**)&kh, g_keys_hi); cudaGetSymbolAddress((void**)&kl, g_keys_lo);
    cudaGetSymbolAddress((void**)&hh, g_hall_hi); cudaGetSymbolAddress((void**)&hl, g_hall_lo);
    cudaGetSymbolAddress((void**)&wh, g_w_hi);    cudaGetSymbolAddress((void**)&wl, g_w_lo);

    cudaMemsetAsync(syncp, 0, (2 + BB * 32) * sizeof(unsigned));

    cudaFuncSetAttribute(decode_loop, cudaFuncAttributeMaxDynamicSharedMemorySize,
                         DYN_FLOATS * (int)sizeof(float));
    cudaFuncSetAttribute(mma_nt, cudaFuncAttributeMaxDynamicSharedMemorySize, MMA_SMEM);

    gather_conv<<<NB_GATH + NB_OUTW + NB_PTCH + NB_KVW + NB_AWK + NB_WIH, 256>>>(
        tgt, emb, outW, patches, kvW, aWk, Wih);

    // keys = patches @ kvW^T + kvb     [6272 x 512], K=768 (also emit bf16 split)
    mma_nt<<<dim3(4, 49), 256, MMA_SMEM>>>(ph, pl, kvh, kvl, kvb, nullptr,
                                           keys, 512, 512, 24, 768, 768, kh, kl);
    // wk = keys @ aWk^T                [6272 x 512], K=512
    mma_nt<<<dim3(4, 49), 256, MMA_SMEM>>>(kh, kl, awh, awl, nullptr, nullptr,
                                           wk, 512, 512, 16, 512, 512, nullptr, nullptr);
    // Gx = x @ Wih_x^T + b_ih + b_hh   [4096 x 2048], K=512
    mma_nt<<<dim3(16, 32), 256, MMA_SMEM>>>(xh, xl, wih_h, wih_l, bih, bhh,
                                            Gx, 2048, 2048, 16, 512, 512, nullptr, nullptr);

    decode_loop<<<GRID_P, 256, DYN_FLOATS * sizeof(float)>>>(
        aWh, av, Wih, Whh, lnw, lnb, cls, ihW, ihb, icW, icb);

    // logits = hall @ outW^T + outb    [4096 x 10000], K=512
    mma_nt<<<dim3(79, 32), 256, MMA_SMEM>>>(hh, hl, wh, wl, outb, nullptr,
                                            out, VV, VV, 16, 512, 512, nullptr, nullptr);
}

// round 15
// speedup vs baseline: 1.4857x; 1.2920x over previous
#include <cuda_runtime.h>
#include <cuda_bf16.h>
#include <math.h>
#include <stdint.h>

#define BB 32
#define NN 196
#define TT 128
#define DH 512
#define VV 10000
#define VPAD 10112
#define GRID_P 128

typedef __nv_bfloat16 bf16;

// decode_loop dynamic smem: 3 banks x (hi+lo) of [32 rows][520 bf16]
#define ROWS32 32
#define KSTR 520
#define BANKE (ROWS32 * KSTR)          // 16640 bf16
#define OFF_WWH 0
#define OFF_WWL (1 * BANKE)
#define OFF_WCH (2 * BANKE)
#define OFF_WCL (3 * BANKE)
#define OFF_AH  (4 * BANKE)
#define OFF_AL  (5 * BANKE)
#define DEC_SMEM (6 * BANKE * 2)       // 199,680 bytes

// ---------------- device scratch (static, no allocation) ----------------
__device__ float g_keys[BB * NN * DH];
__device__ float g_wk  [BB * NN * DH];
__device__ float g_Gx  [BB * TT * 4 * DH];
__device__ float g_c   [BB * DH];
__device__ float g_hwh [BB * DH];
__device__ float g_gh  [BB * 4 * DH];
__device__ float g_gx  [BB * 4 * DH];
__device__ float g_ctxp[4][BB * DH];
__device__ float g_cm[BB * 4], g_cs[BB * 4];
__device__ unsigned g_sync[2 + BB * 32];     // [0]=count [2+b*32]=mini-barriers
__device__ bf16 g_hall_hi[BB * TT * DH], g_hall_lo[BB * TT * DH];
__device__ bf16 g_w_hi[VPAD * DH], g_w_lo[VPAD * DH];   // rows >= VV stay zero
__device__ bf16 g_x_hi[BB * TT * DH], g_x_lo[BB * TT * DH];
__device__ bf16 g_p_hi[BB * NN * 768], g_p_lo[BB * NN * 768];
__device__ bf16 g_kvw_hi[512 * 768], g_kvw_lo[512 * 768];
__device__ bf16 g_awk_hi[512 * 512], g_awk_lo[512 * 512];
__device__ bf16 g_wih_hi[2048 * 512], g_wih_lo[2048 * 512];     // Wih x-half
__device__ bf16 g_keys_hi[BB * NN * DH], g_keys_lo[BB * NN * DH];
__device__ bf16 g_whh_hi[2048 * 512], g_whh_lo[2048 * 512];     // W_hh
__device__ bf16 g_wh_hi[512 * 512],  g_wh_lo[512 * 512];        // attn_Wh
__device__ bf16 g_wihc_hi[2048 * 512], g_wihc_lo[2048 * 512];   // Wih ctx-half
__device__ bf16 g_hb_hi[BB * DH], g_hb_lo[BB * DH];             // current h
__device__ bf16 g_ctxb_hi[BB * DH], g_ctxb_lo[BB * DH];         // current ctx

__device__ __forceinline__ float fast_tanh(float x) {
    float y; asm("tanh.approx.f32 %0, %1;" : "=f"(y) : "f"(x)); return y;
}
__device__ __forceinline__ float sigm(float x) { return 1.f / (1.f + expf(-x)); }
__device__ __forceinline__ void split_bf16(float v, bf16* hi, bf16* lo) {
    const bf16 h = __float2bfloat16(v);
    *hi = h;
    *lo = __float2bfloat16(v - __bfloat162float(h));
}

// release-arrive / acquire-poll primitives
__device__ __forceinline__ void red_release_add(unsigned* p) {
    asm volatile("red.release.gpu.global.add.u32 [%0], %1;" :: "l"(p), "r"(1u) : "memory");
}
__device__ __forceinline__ unsigned ld_acquire(const unsigned* p) {
    unsigned v;
    asm volatile("ld.acquire.gpu.global.u32 %0, [%1];" : "=r"(v) : "l"(p) : "memory");
    return v;
}

// ---------------- mma.sync helpers ----------------
__device__ __forceinline__ uint32_t smem_u32(const void* p) {
    uint32_t a;
    asm("{ .reg .u64 t; cvta.to.shared.u64 t, %1; cvt.u32.u64 %0, t; }" : "=r"(a) : "l"(p));
    return a;
}
__device__ __forceinline__ void ldsm4(uint32_t* r, uint32_t addr) {
    asm volatile("ldmatrix.sync.aligned.m8n8.x4.shared.b16 {%0,%1,%2,%3}, [%4];"
        : "=r"(r[0]), "=r"(r[1]), "=r"(r[2]), "=r"(r[3]) : "r"(addr));
}
__device__ __forceinline__ void ldsm2(uint32_t* r, uint32_t addr) {
    asm volatile("ldmatrix.sync.aligned.m8n8.x2.shared.b16 {%0,%1}, [%2];"
        : "=r"(r[0]), "=r"(r[1]) : "r"(addr));
}
__device__ __forceinline__ void mma16816(float* c, const uint32_t* a, const uint32_t* b) {
    asm volatile("mma.sync.aligned.m16n8k16.row.col.f32.bf16.bf16.f32 "
        "{%0,%1,%2,%3}, {%4,%5,%6,%7}, {%8,%9}, {%0,%1,%2,%3};"
        : "+f"(c[0]), "+f"(c[1]), "+f"(c[2]), "+f"(c[3])
        : "r"(a[0]), "r"(a[1]), "r"(a[2]), "r"(a[3]), "r"(b[0]), "r"(b[1]));
}
__device__ __forceinline__ void cp16(uint32_t smem_addr, const void* gptr) {
    asm volatile("cp.async.cg.shared.global [%0], [%1], 16;"
        :: "r"(smem_addr), "l"(gptr));
}
#define CP_COMMIT() asm volatile("cp.async.commit_group;" ::: "memory")
#define CP_WAIT(n)  asm volatile("cp.async.wait_group %0;" :: "n"(n) : "memory")

// ---------------- generic split-bf16 MMA GEMM (validated) ----------------
#define LSTR 40
#define MAT_B (128 * LSTR * 2)
#define BUF_B (4 * MAT_B)
#define MMA_SMEM (2 * BUF_B)
__global__ __launch_bounds__(256, 2) void mma_nt(
    const bf16* __restrict__ Ah, const bf16* __restrict__ Al,
    const bf16* __restrict__ Bh, const bf16* __restrict__ Bl,
    const float* __restrict__ bias1, const float* __restrict__ bias2,
    float* __restrict__ C, int ldc, int nLimit, int kChunks, int ldA, int ldB,
    bf16* __restrict__ Chi, bf16* __restrict__ Clo)
{
    extern __shared__ char lsm[];
    const uint32_t u0 = smem_u32(lsm);

    const int tid = threadIdx.x;
    const int wid = tid >> 5, lane = tid & 31;
    const int nBase = blockIdx.x * 128;
    const int mBase = blockIdx.y * 128;
    const int wm = (wid & 3) * 32;
    const int wn = (wid >> 2) * 64;

    float acc[2][8][4];
#pragma unroll
    for (int i = 0; i < 2; i++)
#pragma unroll
        for (int j = 0; j < 8; j++)
#pragma unroll
            for (int k = 0; k < 4; k++) acc[i][j][k] = 0.f;

    const int cr = tid >> 1;
    const int cs = (tid & 1) * 2;

    const bf16* gsrc[4] = {
        Ah + (size_t)(mBase + cr) * ldA, Al + (size_t)(mBase + cr) * ldA,
        Bh + (size_t)(nBase + cr) * ldB, Bl + (size_t)(nBase + cr) * ldB };
    const uint32_t sdst = u0 + (cr * LSTR + cs * 8) * 2;

    auto stage = [&](int ch, int buf) {
        const int goff = ch * 32 + cs * 8;
#pragma unroll
        for (int m = 0; m < 4; m++) {
            const uint32_t d = sdst + buf * BUF_B + m * MAT_B;
            cp16(d, gsrc[m] + goff);
            cp16(d + 16, gsrc[m] + goff + 8);
        }
        CP_COMMIT();
    };

    stage(0, 0);

    for (int ch = 0; ch < kChunks; ch++) {
        const int cur = ch & 1;
        if (ch + 1 < kChunks) { stage(ch + 1, cur ^ 1); CP_WAIT(1); }
        else                  { CP_WAIT(0); }
        __syncthreads();

        const uint32_t uAh = u0 + cur * BUF_B;
        const uint32_t uAl = uAh + MAT_B;
        const uint32_t uBh = uAl + MAT_B;
        const uint32_t uBl = uBh + MAT_B;

#pragma unroll
        for (int ks = 0; ks < 2; ks++) {
            uint32_t ah[2][4], al[2][4], bh[8][2], bl[8][2];
#pragma unroll
            for (int mt = 0; mt < 2; mt++) {
                const uint32_t off =
                    ((wm + mt * 16 + (lane & 15)) * LSTR + ks * 16 + (lane >> 4) * 8) * 2;
                ldsm4(ah[mt], uAh + off);
                ldsm4(al[mt], uAl + off);
            }
#pragma unroll
            for (int p = 0; p < 4; p++) {
                const uint32_t off =
                    ((wn + p * 16 + ((lane >> 4) & 1) * 8 + (lane & 7)) * LSTR +
                     ks * 16 + ((lane >> 3) & 1) * 8) * 2;
                uint32_t r4[4];
                ldsm4(r4, uBh + off);
                bh[2 * p][0] = r4[0]; bh[2 * p][1] = r4[1];
                bh[2 * p + 1][0] = r4[2]; bh[2 * p + 1][1] = r4[3];
                ldsm4(r4, uBl + off);
                bl[2 * p][0] = r4[0]; bl[2 * p][1] = r4[1];
                bl[2 * p + 1][0] = r4[2]; bl[2 * p + 1][1] = r4[3];
            }
#pragma unroll
            for (int mt = 0; mt < 2; mt++)
#pragma unroll
                for (int nt = 0; nt < 8; nt++) {
                    mma16816(acc[mt][nt], ah[mt], bh[nt]);
                    mma16816(acc[mt][nt], ah[mt], bl[nt]);
                    mma16816(acc[mt][nt], al[mt], bh[nt]);
                }
        }
        __syncthreads();
    }

    const int erow = lane >> 2;
    const int ecol = (lane & 3) * 2;
#pragma unroll
    for (int mt = 0; mt < 2; mt++) {
#pragma unroll
        for (int nt = 0; nt < 8; nt++) {
            const int gn = nBase + wn + nt * 8 + ecol;
            if (gn >= nLimit) continue;
            float b0 = 0.f, b1 = 0.f;
            if (bias1) { b0 += bias1[gn]; b1 += bias1[gn + 1]; }
            if (bias2) { b0 += bias2[gn]; b1 += bias2[gn + 1]; }
            const int r0 = mBase + wm + mt * 16 + erow;
            const float v00 = acc[mt][nt][0] + b0, v01 = acc[mt][nt][1] + b1;
            const float v10 = acc[mt][nt][2] + b0, v11 = acc[mt][nt][3] + b1;
            if (C) {
                *(float2*)&C[(size_t)r0 * ldc + gn] = make_float2(v00, v01);
                *(float2*)&C[(size_t)(r0 + 8) * ldc + gn] = make_float2(v10, v11);
            }
            if (Chi) {
                const size_t i0 = (size_t)r0 * ldc + gn;
                const size_t i1 = (size_t)(r0 + 8) * ldc + gn;
                split_bf16(v00, &Chi[i0], &Clo[i0]);
                split_bf16(v01, &Chi[i0 + 1], &Clo[i0 + 1]);
                split_bf16(v10, &Chi[i1], &Clo[i1]);
                split_bf16(v11, &Chi[i1 + 1], &Clo[i1 + 1]);
            }
        }
    }
}

// ---------------- all input conversions + embedding gather ----------------
#define NB_GATH 8192
#define NB_OUTW 20000
#define NB_PTCH 18816
#define NB_KVW  1536
#define NB_AWK  1024
#define NB_WIHX 4096
#define NB_WHH  4096
#define NB_WH   1024
#define NB_WIHC 4096
__global__ void gather_conv(const int* __restrict__ ids, const float* __restrict__ emb,
                            const float* __restrict__ outW, const float* __restrict__ patches,
                            const float* __restrict__ kvW, const float* __restrict__ aWk,
                            const float* __restrict__ Wih, const float* __restrict__ Whh,
                            const float* __restrict__ aWh)
{
    int blk = blockIdx.x;
    const int tid = threadIdx.x;
    if (blk < NB_GATH) {
        const int i = blk * 256 + tid;
        const int d = i & (DH - 1);
        const int bt = i >> 9;
        split_bf16(emb[(size_t)ids[bt] * DH + d], &g_x_hi[i], &g_x_lo[i]);
        return;
    }
    blk -= NB_GATH;
    if (blk < NB_OUTW) {
        const int j = blk * 256 + tid;
        if (j < VV * DH) split_bf16(outW[j], &g_w_hi[j], &g_w_lo[j]);
        return;
    }
    blk -= NB_OUTW;
    if (blk < NB_PTCH) {
        const int j = blk * 256 + tid;
        split_bf16(patches[j], &g_p_hi[j], &g_p_lo[j]);
        return;
    }
    blk -= NB_PTCH;
    if (blk < NB_KVW) {
        const int j = blk * 256 + tid;
        split_bf16(kvW[j], &g_kvw_hi[j], &g_kvw_lo[j]);
        return;
    }
    blk -= NB_KVW;
    if (blk < NB_AWK) {
        const int j = blk * 256 + tid;
        split_bf16(aWk[j], &g_awk_hi[j], &g_awk_lo[j]);
        return;
    }
    blk -= NB_AWK;
    if (blk < NB_WIHX) {
        const int j = blk * 256 + tid;
        const int r = j >> 9, c = j & 511;
        split_bf16(Wih[(size_t)r * 1024 + c], &g_wih_hi[j], &g_wih_lo[j]);
        return;
    }
    blk -= NB_WIHX;
    if (blk < NB_WHH) {
        const int j = blk * 256 + tid;
        split_bf16(Whh[j], &g_whh_hi[j], &g_whh_lo[j]);
        return;
    }
    blk -= NB_WHH;
    if (blk < NB_WH) {
        const int j = blk * 256 + tid;
        split_bf16(aWh[j], &g_wh_hi[j], &g_wh_lo[j]);
        return;
    }
    blk -= NB_WH;
    {
        const int j = blk * 256 + tid;
        const int r = j >> 9, c = j & 511;
        split_bf16(Wih[(size_t)r * 1024 + 512 + c], &g_wihc_hi[j], &g_wihc_lo[j]);
    }
}

// ---------------- persistent decode loop: W/C phases on tensor cores ----------------
__global__ __launch_bounds__(256, 1) void decode_loop(
    const float* __restrict__ av,
    const float* __restrict__ lnw, const float* __restrict__ lnb,
    const float* __restrict__ cls,
    const float* __restrict__ ihW, const float* __restrict__ ihb,
    const float* __restrict__ icW, const float* __restrict__ icb)
{
    extern __shared__ bf16 dsm[];
    __shared__ float s_v[512];
    __shared__ float s_hwh[512];
    __shared__ float s_sc[49];
    __shared__ float s_e[64];
    __shared__ float s_r0[8], s_r1[8], s_mv[2];

    const int tid = threadIdx.x;
    const int bid = blockIdx.x;
    const int warp = tid >> 5, lane = tid & 31;
    const int gwarp = bid * 8 + warp;
    const uint32_t u0 = smem_u32(dsm);
    unsigned bt = 0;

    // ---- one-time weight staging into ldmatrix-layout smem ----
    if (bid < 80) {        // W bank: rows [Whh(2048) | Wh(512)]
        for (int idx = tid; idx < ROWS32 * 64; idx += 256) {
            const int row = idx >> 6, seg = idx & 63;
            const int gr = bid * 32 + row;
            const bf16 *sh, *sl;
            if (gr < 2048) { sh = g_whh_hi + (size_t)gr * 512; sl = g_whh_lo + (size_t)gr * 512; }
            else           { sh = g_wh_hi + (size_t)(gr - 2048) * 512; sl = g_wh_lo + (size_t)(gr - 2048) * 512; }
            *(uint4*)(dsm + OFF_WWH + row * KSTR + seg * 8) = *(const uint4*)(sh + seg * 8);
            *(uint4*)(dsm + OFF_WWL + row * KSTR + seg * 8) = *(const uint4*)(sl + seg * 8);
        }
    }
    if (bid < 64) {        // C bank: Wih ctx-half rows
        for (int idx = tid; idx < ROWS32 * 64; idx += 256) {
            const int row = idx >> 6, seg = idx & 63;
            const int gr = bid * 32 + row;
            *(uint4*)(dsm + OFF_WCH + row * KSTR + seg * 8) = *(const uint4*)(g_wihc_hi + (size_t)gr * 512 + seg * 8);
            *(uint4*)(dsm + OFF_WCL + row * KSTR + seg * 8) = *(const uint4*)(g_wihc_lo + (size_t)gr * 512 + seg * 8);
        }
    }
    for (int k = tid; k < 512; k += 256) s_v[k] = av[k];

    auto gsync = [&](unsigned target) {
        __syncthreads();
        if (tid == 0) {
            red_release_add(&g_sync[0]);
            while (ld_acquire(&g_sync[0]) < (unsigned)GRID_P * target) { __nanosleep(20); }
        }
        __syncthreads();
    };

    // mma helper for W/C phases: A = 32x512 staged at OFF_A, B = weight bank
    auto gate_mma = [&](uint32_t uBh, uint32_t uBl, float* acc) {
        const int mt = warp & 1, nt = warp >> 1;      // nt 0..3
        const uint32_t uAh = u0 + OFF_AH * 2, uAl = u0 + OFF_AL * 2;
        const uint32_t a_off = ((mt * 16 + (lane & 15)) * KSTR + (lane >> 4) * 8) * 2;
        const uint32_t b_off = ((nt * 8 + (lane & 7)) * KSTR + ((lane >> 3) & 1) * 8) * 2;
#pragma unroll 4
        for (int ks = 0; ks < 32; ks++) {
            const uint32_t kb = ks * 32;
            uint32_t ah[4], al[4], bh[2], bl[2];
            ldsm4(ah, uAh + a_off + kb);
            ldsm4(al, uAl + a_off + kb);
            ldsm2(bh, uBh + b_off + kb);
            ldsm2(bl, uBl + b_off + kb);
            mma16816(acc, ah, bh);
            mma16816(acc, ah, bl);
            mma16816(acc, al, bh);
        }
    };

    // ---- h0/c0 (folded): write c fp32 and h as bf16 pair ----
    for (int j = gwarp; j < 2 * BB * DH; j += GRID_P * 8) {
        const int sel = (j >= BB * DH);
        const int r = sel ? j - BB * DH : j;
        const int b = r >> 9, d = r & (DH - 1);
        const float4* W4 = (const float4*)((sel ? icW : ihW) + (size_t)d * 768);
        const float4* x4 = (const float4*)(cls + (size_t)b * 768);
        float acc = 0.f;
#pragma unroll
        for (int p = 0; p < 6; p++) {
            float4 w = W4[lane + 32 * p];
            float4 x = x4[lane + 32 * p];
            acc += w.x * x.x + w.y * x.y + w.z * x.z + w.w * x.w;
        }
#pragma unroll
        for (int o = 16; o; o >>= 1) acc += __shfl_xor_sync(0xffffffffu, acc, o);
        if (lane == 0) {
            if (sel) g_c[b * DH + d] = acc + icb[d];
            else     split_bf16(acc + ihb[d], &g_hb_hi[b * DH + d], &g_hb_lo[b * DH + d]);
        }
    }
    gsync(++bt);

    for (int t = 0; t < TT; t++) {
        // ======== Phase W: h-gates + hwh via mma (80 CTAs) ========
        if (bid < 80) {
            for (int idx = tid; idx < 2048; idx += 256) {   // 32x512 bf16 = 2048 uint4
                const int row = idx >> 6, seg = idx & 63;
                *(uint4*)(dsm + OFF_AH + row * KSTR + seg * 8) = *(const uint4*)(g_hb_hi + row * 512 + seg * 8);
                *(uint4*)(dsm + OFF_AL + row * KSTR + seg * 8) = *(const uint4*)(g_hb_lo + row * 512 + seg * 8);
            }
            __syncthreads();
            float acc[4] = {0.f, 0.f, 0.f, 0.f};
            gate_mma(u0 + OFF_WWH * 2, u0 + OFF_WWL * 2, acc);
            const int mt = warp & 1, nt = warp >> 1;
            const int b0 = mt * 16 + (lane >> 2);
            const int r = bid * 32 + nt * 8 + (lane & 3) * 2;
            if (r < 2048) {
                g_gh[b0 * 2048 + r] = acc[0];       g_gh[b0 * 2048 + r + 1] = acc[1];
                g_gh[(b0 + 8) * 2048 + r] = acc[2]; g_gh[(b0 + 8) * 2048 + r + 1] = acc[3];
            } else {
                const int rr = r - 2048;
                g_hwh[b0 * 512 + rr] = acc[0];       g_hwh[b0 * 512 + rr + 1] = acc[1];
                g_hwh[(b0 + 8) * 512 + rr] = acc[2]; g_hwh[(b0 + 8) * 512 + rr + 1] = acc[3];
            }
        }
        gsync(++bt);

        // ======== Phase B: chunk scores + partial ctx + per-b combine (128 CTAs) ========
        {
            const int b = bid >> 2, p = bid & 3;
            for (int k = tid; k < 512; k += 256) s_hwh[k] = g_hwh[b * 512 + k];
            __syncthreads();

            for (int n = warp; n < 49; n += 8) {
                const int ng = p * 49 + n;
                const float4* wk4 = (const float4*)(g_wk + ((size_t)(b * NN + ng)) * 512);
                const float4* hw4 = (const float4*)s_hwh;
                const float4* v4  = (const float4*)s_v;
                float s = 0.f;
#pragma unroll
                for (int i = 0; i < 4; i++) {
                    const float4 a = wk4[lane + 32 * i];
                    const float4 c = hw4[lane + 32 * i];
                    const float4 w = v4[lane + 32 * i];
                    s += fast_tanh(a.x + c.x) * w.x + fast_tanh(a.y + c.y) * w.y +
                         fast_tanh(a.z + c.z) * w.z + fast_tanh(a.w + c.w) * w.w;
                }
#pragma unroll
                for (int o = 16; o; o >>= 1) s += __shfl_xor_sync(0xffffffffu, s, o);
                if (lane == 0) s_sc[n] = s;
            }
            __syncthreads();

            if (warp == 0) {
                const float x0 = (lane < 49) ? s_sc[lane] : -1e30f;
                const float x1 = (lane + 32 < 49) ? s_sc[lane + 32] : -1e30f;
                float m = fmaxf(x0, x1);
#pragma unroll
                for (int o = 16; o; o >>= 1) m = fmaxf(m, __shfl_xor_sync(0xffffffffu, m, o));
                const float e0 = (lane < 49) ? __expf(x0 - m) : 0.f;
                const float e1 = (lane + 32 < 49) ? __expf(x1 - m) : 0.f;
                if (lane < 49) s_e[lane] = e0;
                if (lane + 32 < 49) s_e[lane + 32] = e1;
                float su = e0 + e1;
#pragma unroll
                for (int o = 16; o; o >>= 1) su += __shfl_xor_sync(0xffffffffu, su, o);
                if (lane == 0) { g_cm[b * 4 + p] = m; g_cs[b * 4 + p] = su; }
            }
            __syncthreads();

#pragma unroll
            for (int u = 0; u < 2; u++) {
                const int d = tid + 256 * u;
                const float* Kp = g_keys + ((size_t)(b * NN + p * 49)) * 512 + d;
                float a = 0.f;
#pragma unroll 7
                for (int i = 0; i < 49; i++) a = fmaf(s_e[i], Kp[(size_t)i * 512], a);
                g_ctxp[p][b * 512 + d] = a;
            }

            __syncthreads();
            if (tid == 0) {
                red_release_add(&g_sync[2 + b * 32]);
                while (ld_acquire(&g_sync[2 + b * 32]) < 4u * (unsigned)(t + 1)) { __nanosleep(20); }
            }
            __syncthreads();

            if (tid < 128) {
                const int d = p * 128 + tid;
                const float m0 = g_cm[b*4+0], m1 = g_cm[b*4+1], m2 = g_cm[b*4+2], m3 = g_cm[b*4+3];
                const float m = fmaxf(fmaxf(m0, m1), fmaxf(m2, m3));
                const float e0 = __expf(m0 - m), e1 = __expf(m1 - m);
                const float e2 = __expf(m2 - m), e3 = __expf(m3 - m);
                const float den = e0 * g_cs[b*4+0] + e1 * g_cs[b*4+1] +
                                  e2 * g_cs[b*4+2] + e3 * g_cs[b*4+3];
                const float v = (e0 * g_ctxp[0][b*512+d] + e1 * g_ctxp[1][b*512+d] +
                                 e2 * g_ctxp[2][b*512+d] + e3 * g_ctxp[3][b*512+d]) / den;
                split_bf16(v, &g_ctxb_hi[b * 512 + d], &g_ctxb_lo[b * 512 + d]);
            }
        }
        gsync(++bt);

        // ======== Phase C: ctx-gates via mma (64 CTAs) ========
        if (bid < 64) {
            for (int idx = tid; idx < 2048; idx += 256) {
                const int row = idx >> 6, seg = idx & 63;
                *(uint4*)(dsm + OFF_AH + row * KSTR + seg * 8) = *(const uint4*)(g_ctxb_hi + row * 512 + seg * 8);
                *(uint4*)(dsm + OFF_AL + row * KSTR + seg * 8) = *(const uint4*)(g_ctxb_lo + row * 512 + seg * 8);
            }
            __syncthreads();
            float acc[4] = {0.f, 0.f, 0.f, 0.f};
            gate_mma(u0 + OFF_WCH * 2, u0 + OFF_WCL * 2, acc);
            const int mt = warp & 1, nt = warp >> 1;
            const int b0 = mt * 16 + (lane >> 2);
            const int r = bid * 32 + nt * 8 + (lane & 3) * 2;
            g_gx[b0 * 2048 + r] = acc[0];       g_gx[b0 * 2048 + r + 1] = acc[1];
            g_gx[(b0 + 8) * 2048 + r] = acc[2]; g_gx[(b0 + 8) * 2048 + r + 1] = acc[3];
        }
        gsync(++bt);

        // ======== Phase D: cell + LayerNorm (32 CTAs) ========
        if (bid < BB) {
            const int b = bid;
            const float* Gx = g_Gx + ((size_t)(b * TT + t)) * 2048;
            const float* Gh = g_gh + (size_t)b * 2048;
            const float* Gc = g_gx + (size_t)b * 2048;
            float hr[2];
            float sum = 0.f, ssq = 0.f;
#pragma unroll
            for (int u = 0; u < 2; u++) {
                const int d = tid + 256 * u;
                const float gi = Gx[d]        + Gh[d]        + Gc[d];
                const float gf = Gx[512 + d]  + Gh[512 + d]  + Gc[512 + d];
                const float gg = Gx[1024 + d] + Gh[1024 + d] + Gc[1024 + d];
                const float go = Gx[1536 + d] + Gh[1536 + d] + Gc[1536 + d];
                const float c_old = g_c[b * DH + d];
                const float cn = sigm(gf) * c_old + sigm(gi) * tanhf(gg);
                g_c[b * DH + d] = cn;
                const float h = sigm(go) * tanhf(cn);
                hr[u] = h; sum += h; ssq += h * h;
            }
#pragma unroll
            for (int o = 16; o; o >>= 1) {
                sum += __shfl_xor_sync(0xffffffffu, sum, o);
                ssq += __shfl_xor_sync(0xffffffffu, ssq, o);
            }
            if (lane == 0) { s_r0[warp] = sum; s_r1[warp] = ssq; }
            __syncthreads();
            if (tid < 8) {
                float s = s_r0[tid], qq = s_r1[tid];
#pragma unroll
                for (int o = 4; o; o >>= 1) {
                    s += __shfl_xor_sync(0x000000ffu, s, o);
                    qq += __shfl_xor_sync(0x000000ffu, qq, o);
                }
                if (tid == 0) { s_mv[0] = s * (1.f / DH); s_mv[1] = qq * (1.f / DH); }
            }
            __syncthreads();
            const float mu = s_mv[0];
            const float var = s_mv[1] - mu * mu;
            const float rstd = rsqrtf(var + 1e-5f);
#pragma unroll
            for (int u = 0; u < 2; u++) {
                const int d = tid + 256 * u;
                const float h = (hr[u] - mu) * rstd * lnw[d] + lnb[d];
                const bf16 hi = __float2bfloat16(h);
                const bf16 lo = __float2bfloat16(h - __bfloat162float(hi));
                const size_t idx = ((size_t)(b * TT + t)) * DH + d;
                g_hall_hi[idx] = hi; g_hall_lo[idx] = lo;
                g_hb_hi[b * DH + d] = hi; g_hb_lo[b * DH + d] = lo;
            }
        }
        gsync(++bt);
    }
}

// ---------------- launch ----------------
extern "C" void kernel_launch(void* const* d_in, const int* in_sizes, int n_in,
                              void* d_out, int out_size)
{
    const float* patches = (const float*)d_in[0];
    const float* cls     = (const float*)d_in[1];
    const int*   tgt     = (const int*)  d_in[2];
    const float* emb     = (const float*)d_in[3];
    const float* kvW     = (const float*)d_in[4];
    const float* kvb     = (const float*)d_in[5];
    const float* ihW     = (const float*)d_in[6];
    const float* ihb     = (const float*)d_in[7];
    const float* icW     = (const float*)d_in[8];
    const float* icb     = (const float*)d_in[9];
    const float* aWh     = (const float*)d_in[10];
    const float* aWk     = (const float*)d_in[11];
    const float* av      = (const float*)d_in[12];
    const float* Wih     = (const float*)d_in[13];
    const float* Whh     = (const float*)d_in[14];
    const float* bih     = (const float*)d_in[15];
    const float* bhh     = (const float*)d_in[16];
    const float* lnw     = (const float*)d_in[17];
    const float* lnb     = (const float*)d_in[18];
    const float* outW    = (const float*)d_in[19];
    const float* outb    = (const float*)d_in[20];
    float* out = (float*)d_out;

    float *keys, *wk, *Gx;
    bf16 *xh, *xl, *ph, *pl, *kvh, *kvl, *awh, *awl, *wihx_h, *wihx_l;
    bf16 *kh, *kl, *hh, *hl, *wh, *wl;
    unsigned* syncp;
    cudaGetSymbolAddress((void**)&keys, g_keys);
    cudaGetSymbolAddress((void**)&wk,   g_wk);
    cudaGetSymbolAddress((void**)&Gx,   g_Gx);
    cudaGetSymbolAddress((void**)&syncp, g_sync);
    cudaGetSymbolAddress((void**)&xh, g_x_hi);   cudaGetSymbolAddress((void**)&xl, g_x_lo);
    cudaGetSymbolAddress((void**)&ph, g_p_hi);   cudaGetSymbolAddress((void**)&pl, g_p_lo);
    cudaGetSymbolAddress((void**)&kvh, g_kvw_hi); cudaGetSymbolAddress((void**)&kvl, g_kvw_lo);
    cudaGetSymbolAddress((void**)&awh, g_awk_hi); cudaGetSymbolAddress((void**)&awl, g_awk_lo);
    cudaGetSymbolAddress((void**)&wihx_h, g_wih_hi); cudaGetSymbolAddress((void**)&wihx_l, g_wih_lo);
    cudaGetSymbolAddress((void**)&kh, g_keys_hi); cudaGetSymbolAddress((void**)&kl, g_keys_lo);
    cudaGetSymbolAddress((void**)&hh, g_hall_hi); cudaGetSymbolAddress((void**)&hl, g_hall_lo);
    cudaGetSymbolAddress((void**)&wh, g_w_hi);    cudaGetSymbolAddress((void**)&wl, g_w_lo);

    cudaMemsetAsync(syncp, 0, (2 + BB * 32) * sizeof(unsigned));

    cudaFuncSetAttribute(decode_loop, cudaFuncAttributeMaxDynamicSharedMemorySize, DEC_SMEM);
    cudaFuncSetAttribute(mma_nt, cudaFuncAttributeMaxDynamicSharedMemorySize, MMA_SMEM);

    gather_conv<<<NB_GATH + NB_OUTW + NB_PTCH + NB_KVW + NB_AWK + NB_WIHX + NB_WHH + NB_WH + NB_WIHC, 256>>>(
        tgt, emb, outW, patches, kvW, aWk, Wih, Whh, aWh);

    // keys = patches @ kvW^T + kvb     [6272 x 512], K=768 (also emit bf16 split)
    mma_nt<<<dim3(4, 49), 256, MMA_SMEM>>>(ph, pl, kvh, kvl, kvb, nullptr,
                                           keys, 512, 512, 24, 768, 768, kh, kl);
    // wk = keys @ aWk^T                [6272 x 512], K=512
    mma_nt<<<dim3(4, 49), 256, MMA_SMEM>>>(kh, kl, awh, awl, nullptr, nullptr,
                                           wk, 512, 512, 16, 512, 512, nullptr, nullptr);
    // Gx = x @ Wih_x^T + b_ih + b_hh   [4096 x 2048], K=512
    mma_nt<<<dim3(16, 32), 256, MMA_SMEM>>>(xh, xl, wihx_h, wihx_l, bih, bhh,
                                            Gx, 2048, 2048, 16, 512, 512, nullptr, nullptr);

    decode_loop<<<GRID_P, 256, DEC_SMEM>>>(av, lnw, lnb, cls, ihW, ihb, icW, icb);

    // logits = hall @ outW^T + outb    [4096 x 10000], K=512
    mma_nt<<<dim3(79, 32), 256, MMA_SMEM>>>(hh, hl, wh, wl, outb, nullptr,
                                            out, VV, VV, 16, 512, 512, nullptr, nullptr);
}